// round 13
// baseline (speedup 1.0000x reference)
#include <cuda_runtime.h>
#include <cuda_bf16.h>
#include <cuda_fp16.h>
#include <math.h>
#include <stdint.h>

#define C_   256
#define HW_  4096
#define B_   2
#define NH_  8
#define DH_  32
#define LOG2E 1.4426950408889634f

// ---------------------------------------------------------------------------
// Scratch:
//   g_xh/g_xl   : x transposed+split  [b][hw][c]            bf16
//   g_qkvh/l    : q,k,v fp16 planes   [wi][b][c][hw]        fp16 (q pre-scaled by LOG2E)
//   g_aoh/g_aol : attention out       [b][hw][c]            bf16
//   g_wh/g_wl   : stacked weights     [wi][o][c] (wi: q,k,v,o)  bf16
// ---------------------------------------------------------------------------
__device__ __nv_bfloat16 g_xh[B_ * HW_ * C_];
__device__ __nv_bfloat16 g_xl[B_ * HW_ * C_];
__device__ __half        g_qkvh[3 * B_ * C_ * HW_];
__device__ __half        g_qkvl[3 * B_ * C_ * HW_];
__device__ __nv_bfloat16 g_aoh[B_ * HW_ * C_];
__device__ __nv_bfloat16 g_aol[B_ * HW_ * C_];
__device__ __nv_bfloat16 g_wh[4 * C_ * C_];
__device__ __nv_bfloat16 g_wl[4 * C_ * C_];

// ===========================================================================
// helpers
// ===========================================================================
__device__ __forceinline__ uint32_t smem_u32(const void* p) {
    uint32_t a;
    asm("{ .reg .u64 t; cvta.to.shared.u64 t, %1; cvt.u32.u64 %0, t; }"
        : "=r"(a) : "l"(p));
    return a;
}
__device__ __forceinline__ void cp16(uint32_t saddr, const void* gaddr) {
    asm volatile("cp.async.cg.shared.global [%0], [%1], 16;"
                 :: "r"(saddr), "l"(gaddr));
}
#define CP_COMMIT() asm volatile("cp.async.commit_group;")
#define CP_WAIT(N)  asm volatile("cp.async.wait_group %0;" :: "n"(N))

__device__ __forceinline__ void ldsm_x4(uint32_t a[4], uint32_t addr) {
    asm volatile("ldmatrix.sync.aligned.m8n8.x4.shared.b16 {%0,%1,%2,%3}, [%4];"
                 : "=r"(a[0]), "=r"(a[1]), "=r"(a[2]), "=r"(a[3]) : "r"(addr));
}
__device__ __forceinline__ void ldsm_x4_t(uint32_t a[4], uint32_t addr) {
    asm volatile("ldmatrix.sync.aligned.m8n8.x4.trans.shared.b16 {%0,%1,%2,%3}, [%4];"
                 : "=r"(a[0]), "=r"(a[1]), "=r"(a[2]), "=r"(a[3]) : "r"(addr));
}
__device__ __forceinline__ void mma_bf16(float c[4], const uint32_t a[4],
                                         uint32_t b0, uint32_t b1) {
    asm volatile("mma.sync.aligned.m16n8k16.row.col.f32.bf16.bf16.f32 "
                 "{%0,%1,%2,%3}, {%4,%5,%6,%7}, {%8,%9}, {%0,%1,%2,%3};"
                 : "+f"(c[0]), "+f"(c[1]), "+f"(c[2]), "+f"(c[3])
                 : "r"(a[0]), "r"(a[1]), "r"(a[2]), "r"(a[3]), "r"(b0), "r"(b1));
}
__device__ __forceinline__ void mma_f16(float c[4], const uint32_t a[4],
                                        uint32_t b0, uint32_t b1) {
    asm volatile("mma.sync.aligned.m16n8k16.row.col.f32.f16.f16.f32 "
                 "{%0,%1,%2,%3}, {%4,%5,%6,%7}, {%8,%9}, {%0,%1,%2,%3};"
                 : "+f"(c[0]), "+f"(c[1]), "+f"(c[2]), "+f"(c[3])
                 : "r"(a[0]), "r"(a[1]), "r"(a[2]), "r"(a[3]), "r"(b0), "r"(b1));
}
__device__ __forceinline__ float fexp2(float x) {
    float y; asm("ex2.approx.f32 %0, %1;" : "=f"(y) : "f"(x)); return y;
}
// packed fp16x2 exp2
__device__ __forceinline__ uint32_t ex2h2(uint32_t a) {
    uint32_t d; asm("ex2.approx.f16x2 %0, %1;" : "=r"(d) : "r"(a)); return d;
}
// pack (lo element, hi element) -> f16x2 (first arg in low 16 bits)
__device__ __forceinline__ uint32_t packh(float lo, float hi) {
    uint32_t u; asm("cvt.rn.f16x2.f32 %0, %1, %2;" : "=r"(u) : "f"(hi), "f"(lo));
    return u;
}
__device__ __forceinline__ void split1(float f, __nv_bfloat16& h, __nv_bfloat16& l) {
    h = __float2bfloat16_rn(f);
    l = __float2bfloat16_rn(f - __bfloat162float(h));
}
__device__ __forceinline__ void split1h(float f, __half& h, __half& l) {
    h = __float2half_rn(f);
    l = __float2half_rn(f - __half2float(h));
}

// ===========================================================================
// Weight split: 4 x [256x256] fp32 -> stacked bf16 hi/lo [1024][256]
// ===========================================================================
__global__ __launch_bounds__(256) void wsplit_kernel(
    const float* __restrict__ W0, const float* __restrict__ W1,
    const float* __restrict__ W2, const float* __restrict__ W3)
{
    const int wi = blockIdx.y;
    const float* W = (wi == 0) ? W0 : (wi == 1) ? W1 : (wi == 2) ? W2 : W3;
    const int idx = blockIdx.x * 256 + threadIdx.x;
    __nv_bfloat16 h, l;
    split1(W[idx], h, l);
    g_wh[wi * C_ * C_ + idx] = h;
    g_wl[wi * C_ * C_ + idx] = l;
}

// ===========================================================================
// x transpose+split: [b][c][hw] fp32 -> [b][hw][c] bf16 hi/lo
// ===========================================================================
__global__ __launch_bounds__(256) void xsplit_kernel(const float* __restrict__ x)
{
    __shared__ float tile[32][33];
    const int hw0 = blockIdx.x << 5;
    const int c0  = blockIdx.y << 5;
    const int b   = blockIdx.z;
    const int tx = threadIdx.x, ty = threadIdx.y;   // (32, 8)
    #pragma unroll
    for (int yy = 0; yy < 4; yy++)
        tile[ty + 8 * yy][tx] =
            x[((size_t)b * C_ + c0 + ty + 8 * yy) * HW_ + hw0 + tx];
    __syncthreads();
    #pragma unroll
    for (int yy = 0; yy < 4; yy++) {
        const int hw = hw0 + ty + 8 * yy;
        const int c  = c0 + tx;
        __nv_bfloat16 h, l;
        split1(tile[tx][ty + 8 * yy], h, l);
        g_xh[((size_t)b * HW_ + hw) * C_ + c] = h;
        g_xl[((size_t)b * HW_ + hw) * C_ + c] = l;
    }
}

// ===========================================================================
// Tensor-core projection. 512 threads, 16 warps (4 oM x 4 nN), tile 128x128,
// warp tile 32x32. A = W bf16 planes [o][c], B = X bf16 planes [n][c].
//   mode 0 (qkv): o in 0..767, write fp16 hi/lo to [wi][b][oc][hw]
//                 (q rows pre-scaled by LOG2E)
//   mode 1 (out): o in 0..255, write fp32 gamma*(acc+bias)+resid
// ===========================================================================
#define PJ_PLANE 10240          // 128 rows x 80B
#define PJ_BUF   40960          // 4 planes
#define PJ_SMEM  81920

__global__ __launch_bounds__(512) void proj_mma_kernel(
    const __nv_bfloat16* __restrict__ Wh, const __nv_bfloat16* __restrict__ Wl,
    const float* __restrict__ bias0, const float* __restrict__ bias1,
    const float* __restrict__ bias2,
    const __nv_bfloat16* __restrict__ Xh, const __nv_bfloat16* __restrict__ Xl,
    __half* __restrict__ dsth, __half* __restrict__ dstl,
    float* __restrict__ dstf, const float* __restrict__ resid,
    const float* __restrict__ gamma, int mode)
{
    extern __shared__ char smem[];
    const uint32_t sb = smem_u32(smem);

    const int n0 = blockIdx.x << 7;
    const int m0 = blockIdx.y << 7;
    const int b  = blockIdx.z;
    const int t  = threadIdx.x;
    const int w  = t >> 5, lane = t & 31;
    const int wM = w & 3, wN = w >> 2;
    const int g = lane >> 2, tq = lane & 3;

    // 2048 cp16 per buffer, 4 per thread
    auto load_buf = [&](int kc, uint32_t bufo) {
        #pragma unroll
        for (int i = 0; i < 4; i++) {
            const int idx = t + (i << 9);
            const int p = idx >> 9;
            const int r = idx & 511;
            const int row = r >> 2, ch = r & 3;
            const __nv_bfloat16* src;
            if (p < 2) src = (p ? Wl : Wh) + (size_t)(m0 + row) * C_ + kc * 32 + ch * 8;
            else       src = (p == 3 ? Xl : Xh)
                           + ((size_t)b * HW_ + n0 + row) * C_ + kc * 32 + ch * 8;
            cp16(sb + bufo + p * PJ_PLANE + row * 80 + ch * 16, src);
        }
        CP_COMMIT();
    };

    load_buf(0, 0);

    float racc[2][4][4] = {};

    const int arow = (lane & 7) + ((lane >> 3) & 1) * 8;
    const int acol = ((lane >> 4) & 1) * 16;            // k-half bytes
    const int brow = (lane & 7);
    const int bsel8  = ((lane >> 3) & 1) * 16;          // k-half bytes
    const int bsel16 = ((lane >> 4) & 1) * 8;           // n +8 rows

    for (int kc = 0; kc < 8; kc++) {
        const uint32_t bufC = (uint32_t)(kc & 1) * PJ_BUF;
        if (kc < 7) load_buf(kc + 1, (uint32_t)((kc + 1) & 1) * PJ_BUF);
        if (kc < 7) { CP_WAIT(1); } else { CP_WAIT(0); }
        __syncthreads();

        #pragma unroll
        for (int kk = 0; kk < 2; kk++) {
            uint32_t aW[2][2][4];   // [plane][mf][4]
            #pragma unroll
            for (int p = 0; p < 2; p++)
                #pragma unroll
                for (int mf = 0; mf < 2; mf++)
                    ldsm_x4(aW[p][mf],
                        sb + bufC + p * PJ_PLANE
                           + (wM * 32 + mf * 16 + arow) * 80 + kk * 32 + acol);

            #pragma unroll
            for (int jp = 0; jp < 2; jp++) {
                uint32_t bh4[4], bl4[4];
                const uint32_t baddr = (wN * 32 + jp * 16 + bsel16 + brow) * 80
                                     + kk * 32 + bsel8;
                ldsm_x4(bh4, sb + bufC + 2 * PJ_PLANE + baddr);
                ldsm_x4(bl4, sb + bufC + 3 * PJ_PLANE + baddr);
                #pragma unroll
                for (int mf = 0; mf < 2; mf++) {
                    mma_bf16(racc[mf][2*jp],   aW[0][mf], bh4[0], bh4[1]);
                    mma_bf16(racc[mf][2*jp+1], aW[0][mf], bh4[2], bh4[3]);
                    mma_bf16(racc[mf][2*jp],   aW[1][mf], bh4[0], bh4[1]);
                    mma_bf16(racc[mf][2*jp+1], aW[1][mf], bh4[2], bh4[3]);
                    mma_bf16(racc[mf][2*jp],   aW[0][mf], bl4[0], bl4[1]);
                    mma_bf16(racc[mf][2*jp+1], aW[0][mf], bl4[2], bl4[3]);
                }
            }
        }
        __syncthreads();
    }

    // epilogue
    const float gm = (mode == 1) ? gamma[0] : 0.0f;
    #pragma unroll
    for (int mf = 0; mf < 2; mf++) {
        #pragma unroll
        for (int half = 0; half < 2; half++) {
            const int o = m0 + wM * 32 + mf * 16 + g + half * 8;
            #pragma unroll
            for (int j = 0; j < 4; j++) {
                const int n = n0 + wN * 32 + j * 8 + tq * 2;
                const float v0r = racc[mf][j][half * 2 + 0];
                const float v1r = racc[mf][j][half * 2 + 1];
                if (mode == 0) {
                    const int wi = o >> 8, oc = o & 255;
                    const float* bp = (wi == 0) ? bias0 : (wi == 1) ? bias1 : bias2;
                    const float bia = bp[oc];
                    const float sc = (wi == 0) ? LOG2E : 1.0f;  // q pre-scaled
                    const size_t idx = (((size_t)wi * B_ + b) * C_ + oc) * HW_ + n;
                    __half h0, l0, h1, l1;
                    split1h((v0r + bia) * sc, h0, l0);
                    split1h((v1r + bia) * sc, h1, l1);
                    *(__half2*)&dsth[idx] = __half2(h0, h1);
                    *(__half2*)&dstl[idx] = __half2(l0, l1);
                } else {
                    const float bia = bias0[o];
                    const size_t idx = ((size_t)b * C_ + o) * HW_ + n;
                    const float2 rr = *(const float2*)&resid[idx];
                    float2 r;
                    r.x = gm * (v0r + bia) + rr.x;
                    r.y = gm * (v1r + bia) + rr.y;
                    *(float2*)&dstf[idx] = r;
                }
            }
        }
    }
}

// ===========================================================================
// HMMA flash attention v8: Bc=128, SOFTWARE-PIPELINED chunks — per 32-m chunk
// order is softmax(cur) -> issue S-MMAs(next) -> PV(cur), so S-MMA results
// drain behind PV/softmax of the previous chunk. 32-m online softmax,
// ex2.f16x2, L via ones-column MMA. 256-query CTA, 8 warps, 2 CTAs/SM.
// S is in log2 domain (q pre-scaled by LOG2E).
// ===========================================================================
#define AQ_OFF 0
#define AQ_ROW 528
#define AQ_PLANE (32 * AQ_ROW)                       // 16896
#define AK_OFF (AQ_OFF + 2 * AQ_PLANE)               // 33792
#define AKV_ROW 272                                  // 128 m * 2B + 16 pad
#define AKV_PLANE (32 * AKV_ROW)                     // 8704
#define AK_BUF (2 * AKV_PLANE)                       // 17408 (hi+lo)
#define AV_OFF (AK_OFF + 2 * AK_BUF)                 // 68608
#define AT_SMEM (AV_OFF + 2 * AKV_PLANE)             // 86016

__global__ __launch_bounds__(256, 2) void attn_mma_kernel(
    const __half* __restrict__ qkvh, const __half* __restrict__ qkvl,
    __nv_bfloat16* __restrict__ oh, __nv_bfloat16* __restrict__ ol)
{
    extern __shared__ char smem[];
    const uint32_t sb = smem_u32(smem);

    const int bh = blockIdx.y;
    const int q0 = blockIdx.x << 8;
    const int t  = threadIdx.x;
    const int w  = t >> 5;
    const int lane = t & 31;
    const int g = lane >> 2, tq = lane & 3;
    const int b = bh >> 3, hh = bh & 7;

    const size_t qoff = (((size_t)0 * B_ + b) * C_ + hh * DH_) * HW_;
    const size_t koff = (((size_t)1 * B_ + b) * C_ + hh * DH_) * HW_;
    const size_t voff = (((size_t)2 * B_ + b) * C_ + hh * DH_) * HW_;
    const __half* qp0 = qkvh + qoff;
    const __half* qp1 = qkvl + qoff;
    const __half* kvp0 = qkvh + koff;
    const __half* kvp1 = qkvl + koff;
    const __half* kvp2 = qkvh + voff;

    // ---- issue Q (2 planes, 2048 cp16) + KV iter0 (1536 cp16)
    {
        #pragma unroll
        for (int i = 0; i < 8; i++) {
            const int idx = t + (i << 8);
            const int p = idx >> 10;
            const int r = idx & 1023;
            const int d = r >> 5, ch = r & 31;
            const __half* src = (p ? qp1 : qp0) + (size_t)d * HW_ + q0 + ch * 8;
            cp16(sb + AQ_OFF + p * AQ_PLANE + d * AQ_ROW + ch * 16, src);
        }
        #pragma unroll
        for (int i = 0; i < 6; i++) {
            const int idx = t + (i << 8);
            const int p3 = idx >> 9;           // 0 kh, 1 kl, 2 vh
            const int r = idx & 511;
            const int d = r >> 4, ch = r & 15;
            const __half* src = (p3 == 0 ? kvp0 : p3 == 1 ? kvp1 : kvp2)
                              + (size_t)d * HW_ + ch * 8;
            const uint32_t so = (p3 < 2) ? (AK_OFF + p3 * AKV_PLANE) : AV_OFF;
            cp16(sb + so + d * AKV_ROW + ch * 16, src);
        }
        CP_COMMIT();
    }
    CP_WAIT(0);
    __syncthreads();

    // lane addressing
    const int qrow = (lane & 7) + ((lane >> 4) << 3);
    const int qsel = ((lane >> 3) & 1) << 3;
    const uint32_t qbase = sb + AQ_OFF + qrow * AQ_ROW + (w * 32 + qsel) * 2;
    const int kRowD = (lane & 7) + ((lane >> 4) << 3);
    const int kColB = ((lane >> 3) & 1) * 16;
    const int vRowP = (lane & 7) + (((lane >> 4) & 1) << 3);
    const int vColB = ((lane >> 3) & 1) * 16;

    float oacc[2][4][4] = {};
    float oL[2][4] = {};
    float M0[2] = { -INFINITY, -INFINITY };
    float M1[2] = { -INFINITY, -INFINITY };
    const uint32_t bOnes = (lane < 4) ? 0x3C003C00u : 0u;   // ones in col 0

    // S computation for one 32-m chunk into sc
    auto computeS = [&](float (&sc)[2][4][4], int jc, uint32_t kBuf) {
        #pragma unroll
        for (int mf = 0; mf < 2; mf++)
            #pragma unroll
            for (int nb = 0; nb < 4; nb++)
                #pragma unroll
                for (int e = 0; e < 4; e++) sc[mf][nb][e] = 0.0f;
        #pragma unroll
        for (int s = 0; s < 2; s++) {
            uint32_t aQs[2][2][4];   // [plane][mf][4]
            #pragma unroll
            for (int p = 0; p < 2; p++)
                #pragma unroll
                for (int mf = 0; mf < 2; mf++)
                    ldsm_x4_t(aQs[p][mf],
                        qbase + p * AQ_PLANE + s * 16 * AQ_ROW + mf * 32);
            #pragma unroll
            for (int jpi = 0; jpi < 2; jpi++) {
                const int jp = jc * 2 + jpi;
                uint32_t kh4[4], kl4[4];
                const uint32_t ka = kBuf + ((s << 4) + kRowD) * AKV_ROW
                                  + jp * 32 + kColB;
                ldsm_x4_t(kh4, sb + AK_OFF + ka);
                ldsm_x4_t(kl4, sb + AK_OFF + AKV_PLANE + ka);
                #pragma unroll
                for (int mf = 0; mf < 2; mf++) {
                    mma_f16(sc[mf][2*jpi],   aQs[0][mf], kh4[0], kh4[2]);
                    mma_f16(sc[mf][2*jpi+1], aQs[0][mf], kh4[1], kh4[3]);
                    mma_f16(sc[mf][2*jpi],   aQs[1][mf], kh4[0], kh4[2]);
                    mma_f16(sc[mf][2*jpi+1], aQs[1][mf], kh4[1], kh4[3]);
                    mma_f16(sc[mf][2*jpi],   aQs[0][mf], kl4[0], kl4[2]);
                    mma_f16(sc[mf][2*jpi+1], aQs[0][mf], kl4[1], kl4[3]);
                }
            }
        }
    };

    float scA[2][4][4], scB[2][4][4];

    for (int i = 0; i < 32; i++) {
        const uint32_t kBuf = (uint32_t)(i & 1) * AK_BUF;
        const uint32_t vBuf = (uint32_t)(i & 1) * AKV_PLANE;
        if (i < 31) {
            const int m0n = (i + 1) << 7;
            const uint32_t kBufN = (uint32_t)((i + 1) & 1) * AK_BUF;
            const uint32_t vBufN = (uint32_t)((i + 1) & 1) * AKV_PLANE;
            #pragma unroll
            for (int u = 0; u < 6; u++) {
                const int idx = t + (u << 8);
                const int p3 = idx >> 9;
                const int r = idx & 511;
                const int d = r >> 4, ch = r & 15;
                const __half* src = (p3 == 0 ? kvp0 : p3 == 1 ? kvp1 : kvp2)
                                  + (size_t)d * HW_ + m0n + ch * 8;
                const uint32_t so = (p3 < 2) ? (AK_OFF + kBufN + p3 * AKV_PLANE)
                                             : (AV_OFF + vBufN);
                cp16(sb + so + d * AKV_ROW + ch * 16, src);
            }
            CP_COMMIT();
            CP_WAIT(1);
        } else {
            CP_WAIT(0);
        }
        __syncthreads();

        // ---- pipelined 4-chunk window: S(0) exposed, rest hidden behind PV
        computeS(scA, 0, kBuf);

        #pragma unroll
        for (int jc = 0; jc < 4; jc++) {
            float (&cur)[2][4][4] = (jc & 1) ? scB : scA;
            float (&nxt)[2][4][4] = (jc & 1) ? scA : scB;

            // ---- online softmax over chunk jc (results long since drained)
            uint32_t ah[2][2][4];   // [mf][jpi][4] packed fp16 P
            #pragma unroll
            for (int mf = 0; mf < 2; mf++) {
                float c0 = fmaxf(
                    fmaxf(fmaxf(cur[mf][0][0], cur[mf][0][1]),
                          fmaxf(cur[mf][1][0], cur[mf][1][1])),
                    fmaxf(fmaxf(cur[mf][2][0], cur[mf][2][1]),
                          fmaxf(cur[mf][3][0], cur[mf][3][1])));
                float c1 = fmaxf(
                    fmaxf(fmaxf(cur[mf][0][2], cur[mf][0][3]),
                          fmaxf(cur[mf][1][2], cur[mf][1][3])),
                    fmaxf(fmaxf(cur[mf][2][2], cur[mf][2][3]),
                          fmaxf(cur[mf][3][2], cur[mf][3][3])));
                c0 = fmaxf(c0, __shfl_xor_sync(0xffffffffu, c0, 1));
                c0 = fmaxf(c0, __shfl_xor_sync(0xffffffffu, c0, 2));
                c1 = fmaxf(c1, __shfl_xor_sync(0xffffffffu, c1, 1));
                c1 = fmaxf(c1, __shfl_xor_sync(0xffffffffu, c1, 2));

                const float Mn0 = fmaxf(M0[mf], c0);
                const float al0 = fexp2(M0[mf] - Mn0);
                M0[mf] = Mn0;
                const float Mn1 = fmaxf(M1[mf], c1);
                const float al1 = fexp2(M1[mf] - Mn1);
                M1[mf] = Mn1;

                #pragma unroll
                for (int dj = 0; dj < 4; dj++) {
                    oacc[mf][dj][0] *= al0; oacc[mf][dj][1] *= al0;
                    oacc[mf][dj][2] *= al1; oacc[mf][dj][3] *= al1;
                }
                oL[mf][0] *= al0; oL[mf][2] *= al1;

                #pragma unroll
                for (int nb = 0; nb < 4; nb++) {
                    const float t0 = cur[mf][nb][0] - Mn0;
                    const float t1 = cur[mf][nb][1] - Mn0;
                    const float t2 = cur[mf][nb][2] - Mn1;
                    const float t3 = cur[mf][nb][3] - Mn1;
                    ah[mf][nb >> 1][(nb & 1) * 2 + 0] = ex2h2(packh(t0, t1));
                    ah[mf][nb >> 1][(nb & 1) * 2 + 1] = ex2h2(packh(t2, t3));
                }
            }

            // ---- issue next chunk's S-MMAs (drain behind PV below)
            if (jc < 3) computeS(nxt, jc + 1, kBuf);

            // ---- PV + L-column for chunk jc
            #pragma unroll
            for (int jpi = 0; jpi < 2; jpi++) {
                const int jp = jc * 2 + jpi;
                #pragma unroll
                for (int jpd = 0; jpd < 2; jpd++) {
                    uint32_t vh4[4];
                    ldsm_x4(vh4, sb + AV_OFF + vBuf
                                 + (jpd * 16 + vRowP) * AKV_ROW
                                 + jp * 32 + vColB);
                    #pragma unroll
                    for (int mf = 0; mf < 2; mf++) {
                        mma_f16(oacc[mf][2*jpd],   ah[mf][jpi], vh4[0], vh4[1]);
                        mma_f16(oacc[mf][2*jpd+1], ah[mf][jpi], vh4[2], vh4[3]);
                    }
                }
                #pragma unroll
                for (int mf = 0; mf < 2; mf++)
                    mma_f16(oL[mf], ah[mf][jpi], bOnes, bOnes);
            }
        }
        __syncthreads();
    }

    // ---- epilogue: broadcast L from tq==0 lanes, normalize, split, store
    #pragma unroll
    for (int mf = 0; mf < 2; mf++) {
        const float L0 = __shfl_sync(0xffffffffu, oL[mf][0], lane & 28);
        const float L1 = __shfl_sync(0xffffffffu, oL[mf][2], lane & 28);
        const float inv0 = 1.0f / L0;
        const float inv1 = 1.0f / L1;
        #pragma unroll
        for (int h = 0; h < 2; h++) {
            const float inv = h ? inv1 : inv0;
            const int hw = q0 + w * 32 + mf * 16 + g + h * 8;
            #pragma unroll
            for (int dj = 0; dj < 4; dj++) {
                const int d = 8 * dj + tq * 2;
                const float v0 = oacc[mf][dj][h * 2 + 0] * inv;
                const float v1 = oacc[mf][dj][h * 2 + 1] * inv;
                __nv_bfloat16 h0, l0, h1, l1;
                split1(v0, h0, l0); split1(v1, h1, l1);
                const size_t idx = ((size_t)b * HW_ + hw) * C_ + hh * 32 + d;
                *(__nv_bfloat162*)&oh[idx] = __nv_bfloat162(h0, h1);
                *(__nv_bfloat162*)&ol[idx] = __nv_bfloat162(l0, l1);
            }
        }
    }
}

// ===========================================================================
extern "C" void kernel_launch(void* const* d_in, const int* in_sizes, int n_in,
                              void* d_out, int out_size)
{
    const float* x     = (const float*)d_in[0];
    const float* Wq    = (const float*)d_in[1];
    const float* bq    = (const float*)d_in[2];
    const float* Wk    = (const float*)d_in[3];
    const float* bk    = (const float*)d_in[4];
    const float* Wv    = (const float*)d_in[5];
    const float* bv    = (const float*)d_in[6];
    const float* Wo    = (const float*)d_in[7];
    const float* bo    = (const float*)d_in[8];
    const float* gamma = (const float*)d_in[9];
    float* out = (float*)d_out;

    __nv_bfloat16 *xh, *xl, *aoh, *aol, *wh, *wl;
    __half *qkvh, *qkvl;
    cudaGetSymbolAddress((void**)&xh,   g_xh);
    cudaGetSymbolAddress((void**)&xl,   g_xl);
    cudaGetSymbolAddress((void**)&qkvh, g_qkvh);
    cudaGetSymbolAddress((void**)&qkvl, g_qkvl);
    cudaGetSymbolAddress((void**)&aoh,  g_aoh);
    cudaGetSymbolAddress((void**)&aol,  g_aol);
    cudaGetSymbolAddress((void**)&wh,   g_wh);
    cudaGetSymbolAddress((void**)&wl,   g_wl);

    cudaFuncSetAttribute(proj_mma_kernel,
                         cudaFuncAttributeMaxDynamicSharedMemorySize, PJ_SMEM);
    cudaFuncSetAttribute(attn_mma_kernel,
                         cudaFuncAttributeMaxDynamicSharedMemorySize, AT_SMEM);

    wsplit_kernel<<<dim3(256, 4), 256>>>(Wq, Wk, Wv, Wo);
    xsplit_kernel<<<dim3(HW_ / 32, C_ / 32, B_), dim3(32, 8)>>>(x);

    // fused QKV projection: M = 768
    proj_mma_kernel<<<dim3(HW_ / 128, 6, B_), 512, PJ_SMEM>>>(
        wh, wl, bq, bk, bv, xh, xl, qkvh, qkvl, nullptr, nullptr, nullptr, 0);

    attn_mma_kernel<<<dim3(HW_ / 256, B_ * NH_), 256, AT_SMEM>>>(
        qkvh, qkvl, aoh, aol);

    // output projection: W rows 768..1023
    proj_mma_kernel<<<dim3(HW_ / 128, 2, B_), 512, PJ_SMEM>>>(
        wh + 3 * C_ * C_, wl + 3 * C_ * C_, bo, nullptr, nullptr,
        aoh, aol, nullptr, nullptr, out, x, gamma, 1);
}

// round 15
// speedup vs baseline: 1.1538x; 1.1538x over previous
#include <cuda_runtime.h>
#include <cuda_bf16.h>
#include <cuda_fp16.h>
#include <math.h>
#include <stdint.h>

#define C_   256
#define HW_  4096
#define B_   2
#define NH_  8
#define DH_  32
#define LOG2E 1.4426950408889634f

// ---------------------------------------------------------------------------
// Scratch:
//   g_xh/g_xl   : x transposed+split  [b][hw][c]            bf16
//   g_qkvh/l    : q,k,v fp16 planes   [wi][b][c][hw]        fp16 (q pre-scaled by LOG2E)
//   g_aoh/g_aol : attention out       [b][hw][c]            bf16
//   g_wh/g_wl   : stacked weights     [wi][o][c] (wi: q,k,v,o)  bf16
// ---------------------------------------------------------------------------
__device__ __nv_bfloat16 g_xh[B_ * HW_ * C_];
__device__ __nv_bfloat16 g_xl[B_ * HW_ * C_];
__device__ __half        g_qkvh[3 * B_ * C_ * HW_];
__device__ __half        g_qkvl[3 * B_ * C_ * HW_];
__device__ __nv_bfloat16 g_aoh[B_ * HW_ * C_];
__device__ __nv_bfloat16 g_aol[B_ * HW_ * C_];
__device__ __nv_bfloat16 g_wh[4 * C_ * C_];
__device__ __nv_bfloat16 g_wl[4 * C_ * C_];

// ===========================================================================
// helpers
// ===========================================================================
__device__ __forceinline__ uint32_t smem_u32(const void* p) {
    uint32_t a;
    asm("{ .reg .u64 t; cvta.to.shared.u64 t, %1; cvt.u32.u64 %0, t; }"
        : "=r"(a) : "l"(p));
    return a;
}
__device__ __forceinline__ void cp16(uint32_t saddr, const void* gaddr) {
    asm volatile("cp.async.cg.shared.global [%0], [%1], 16;"
                 :: "r"(saddr), "l"(gaddr));
}
#define CP_COMMIT() asm volatile("cp.async.commit_group;")
#define CP_WAIT(N)  asm volatile("cp.async.wait_group %0;" :: "n"(N))

__device__ __forceinline__ void ldsm_x4(uint32_t a[4], uint32_t addr) {
    asm volatile("ldmatrix.sync.aligned.m8n8.x4.shared.b16 {%0,%1,%2,%3}, [%4];"
                 : "=r"(a[0]), "=r"(a[1]), "=r"(a[2]), "=r"(a[3]) : "r"(addr));
}
__device__ __forceinline__ void ldsm_x4_t(uint32_t a[4], uint32_t addr) {
    asm volatile("ldmatrix.sync.aligned.m8n8.x4.trans.shared.b16 {%0,%1,%2,%3}, [%4];"
                 : "=r"(a[0]), "=r"(a[1]), "=r"(a[2]), "=r"(a[3]) : "r"(addr));
}
__device__ __forceinline__ void mma_bf16(float c[4], const uint32_t a[4],
                                         uint32_t b0, uint32_t b1) {
    asm volatile("mma.sync.aligned.m16n8k16.row.col.f32.bf16.bf16.f32 "
                 "{%0,%1,%2,%3}, {%4,%5,%6,%7}, {%8,%9}, {%0,%1,%2,%3};"
                 : "+f"(c[0]), "+f"(c[1]), "+f"(c[2]), "+f"(c[3])
                 : "r"(a[0]), "r"(a[1]), "r"(a[2]), "r"(a[3]), "r"(b0), "r"(b1));
}
__device__ __forceinline__ void mma_f16(float c[4], const uint32_t a[4],
                                        uint32_t b0, uint32_t b1) {
    asm volatile("mma.sync.aligned.m16n8k16.row.col.f32.f16.f16.f32 "
                 "{%0,%1,%2,%3}, {%4,%5,%6,%7}, {%8,%9}, {%0,%1,%2,%3};"
                 : "+f"(c[0]), "+f"(c[1]), "+f"(c[2]), "+f"(c[3])
                 : "r"(a[0]), "r"(a[1]), "r"(a[2]), "r"(a[3]), "r"(b0), "r"(b1));
}
__device__ __forceinline__ float fexp2(float x) {
    float y; asm("ex2.approx.f32 %0, %1;" : "=f"(y) : "f"(x)); return y;
}
// packed fp16x2 exp2
__device__ __forceinline__ uint32_t ex2h2(uint32_t a) {
    uint32_t d; asm("ex2.approx.f16x2 %0, %1;" : "=r"(d) : "r"(a)); return d;
}
// pack (lo element, hi element) -> f16x2 (first arg in low 16 bits)
__device__ __forceinline__ uint32_t packh(float lo, float hi) {
    uint32_t u; asm("cvt.rn.f16x2.f32 %0, %1, %2;" : "=r"(u) : "f"(hi), "f"(lo));
    return u;
}
__device__ __forceinline__ void split1(float f, __nv_bfloat16& h, __nv_bfloat16& l) {
    h = __float2bfloat16_rn(f);
    l = __float2bfloat16_rn(f - __bfloat162float(h));
}
__device__ __forceinline__ void split1h(float f, __half& h, __half& l) {
    h = __float2half_rn(f);
    l = __float2half_rn(f - __half2float(h));
}

// ===========================================================================
// Weight split: 4 x [256x256] fp32 -> stacked bf16 hi/lo [1024][256]
// ===========================================================================
__global__ __launch_bounds__(256) void wsplit_kernel(
    const float* __restrict__ W0, const float* __restrict__ W1,
    const float* __restrict__ W2, const float* __restrict__ W3)
{
    const int wi = blockIdx.y;
    const float* W = (wi == 0) ? W0 : (wi == 1) ? W1 : (wi == 2) ? W2 : W3;
    const int idx = blockIdx.x * 256 + threadIdx.x;
    __nv_bfloat16 h, l;
    split1(W[idx], h, l);
    g_wh[wi * C_ * C_ + idx] = h;
    g_wl[wi * C_ * C_ + idx] = l;
}

// ===========================================================================
// x transpose+split: [b][c][hw] fp32 -> [b][hw][c] bf16 hi/lo
// ===========================================================================
__global__ __launch_bounds__(256) void xsplit_kernel(const float* __restrict__ x)
{
    __shared__ float tile[32][33];
    const int hw0 = blockIdx.x << 5;
    const int c0  = blockIdx.y << 5;
    const int b   = blockIdx.z;
    const int tx = threadIdx.x, ty = threadIdx.y;   // (32, 8)
    #pragma unroll
    for (int yy = 0; yy < 4; yy++)
        tile[ty + 8 * yy][tx] =
            x[((size_t)b * C_ + c0 + ty + 8 * yy) * HW_ + hw0 + tx];
    __syncthreads();
    #pragma unroll
    for (int yy = 0; yy < 4; yy++) {
        const int hw = hw0 + ty + 8 * yy;
        const int c  = c0 + tx;
        __nv_bfloat16 h, l;
        split1(tile[tx][ty + 8 * yy], h, l);
        g_xh[((size_t)b * HW_ + hw) * C_ + c] = h;
        g_xl[((size_t)b * HW_ + hw) * C_ + c] = l;
    }
}

// ===========================================================================
// Tensor-core projection. 512 threads, 16 warps (4 oM x 4 nN), tile 128x128,
// warp tile 32x32. A = W bf16 planes [o][c], B = X bf16 planes [n][c].
//   mode 0 (qkv): o in 0..767, write fp16 hi/lo to [wi][b][oc][hw]
//                 (q rows pre-scaled by LOG2E)
//   mode 1 (out): o in 0..255, write fp32 gamma*(acc+bias)+resid
// ===========================================================================
#define PJ_PLANE 10240          // 128 rows x 80B
#define PJ_BUF   40960          // 4 planes
#define PJ_SMEM  81920

__global__ __launch_bounds__(512) void proj_mma_kernel(
    const __nv_bfloat16* __restrict__ Wh, const __nv_bfloat16* __restrict__ Wl,
    const float* __restrict__ bias0, const float* __restrict__ bias1,
    const float* __restrict__ bias2,
    const __nv_bfloat16* __restrict__ Xh, const __nv_bfloat16* __restrict__ Xl,
    __half* __restrict__ dsth, __half* __restrict__ dstl,
    float* __restrict__ dstf, const float* __restrict__ resid,
    const float* __restrict__ gamma, int mode)
{
    extern __shared__ char smem[];
    const uint32_t sb = smem_u32(smem);

    const int n0 = blockIdx.x << 7;
    const int m0 = blockIdx.y << 7;
    const int b  = blockIdx.z;
    const int t  = threadIdx.x;
    const int w  = t >> 5, lane = t & 31;
    const int wM = w & 3, wN = w >> 2;
    const int g = lane >> 2, tq = lane & 3;

    // 2048 cp16 per buffer, 4 per thread
    auto load_buf = [&](int kc, uint32_t bufo) {
        #pragma unroll
        for (int i = 0; i < 4; i++) {
            const int idx = t + (i << 9);
            const int p = idx >> 9;
            const int r = idx & 511;
            const int row = r >> 2, ch = r & 3;
            const __nv_bfloat16* src;
            if (p < 2) src = (p ? Wl : Wh) + (size_t)(m0 + row) * C_ + kc * 32 + ch * 8;
            else       src = (p == 3 ? Xl : Xh)
                           + ((size_t)b * HW_ + n0 + row) * C_ + kc * 32 + ch * 8;
            cp16(sb + bufo + p * PJ_PLANE + row * 80 + ch * 16, src);
        }
        CP_COMMIT();
    };

    load_buf(0, 0);

    float racc[2][4][4] = {};

    const int arow = (lane & 7) + ((lane >> 3) & 1) * 8;
    const int acol = ((lane >> 4) & 1) * 16;            // k-half bytes
    const int brow = (lane & 7);
    const int bsel8  = ((lane >> 3) & 1) * 16;          // k-half bytes
    const int bsel16 = ((lane >> 4) & 1) * 8;           // n +8 rows

    for (int kc = 0; kc < 8; kc++) {
        const uint32_t bufC = (uint32_t)(kc & 1) * PJ_BUF;
        if (kc < 7) load_buf(kc + 1, (uint32_t)((kc + 1) & 1) * PJ_BUF);
        if (kc < 7) { CP_WAIT(1); } else { CP_WAIT(0); }
        __syncthreads();

        #pragma unroll
        for (int kk = 0; kk < 2; kk++) {
            uint32_t aW[2][2][4];   // [plane][mf][4]
            #pragma unroll
            for (int p = 0; p < 2; p++)
                #pragma unroll
                for (int mf = 0; mf < 2; mf++)
                    ldsm_x4(aW[p][mf],
                        sb + bufC + p * PJ_PLANE
                           + (wM * 32 + mf * 16 + arow) * 80 + kk * 32 + acol);

            #pragma unroll
            for (int jp = 0; jp < 2; jp++) {
                uint32_t bh4[4], bl4[4];
                const uint32_t baddr = (wN * 32 + jp * 16 + bsel16 + brow) * 80
                                     + kk * 32 + bsel8;
                ldsm_x4(bh4, sb + bufC + 2 * PJ_PLANE + baddr);
                ldsm_x4(bl4, sb + bufC + 3 * PJ_PLANE + baddr);
                #pragma unroll
                for (int mf = 0; mf < 2; mf++) {
                    mma_bf16(racc[mf][2*jp],   aW[0][mf], bh4[0], bh4[1]);
                    mma_bf16(racc[mf][2*jp+1], aW[0][mf], bh4[2], bh4[3]);
                    mma_bf16(racc[mf][2*jp],   aW[1][mf], bh4[0], bh4[1]);
                    mma_bf16(racc[mf][2*jp+1], aW[1][mf], bh4[2], bh4[3]);
                    mma_bf16(racc[mf][2*jp],   aW[0][mf], bl4[0], bl4[1]);
                    mma_bf16(racc[mf][2*jp+1], aW[0][mf], bl4[2], bl4[3]);
                }
            }
        }
        __syncthreads();
    }

    // epilogue
    const float gm = (mode == 1) ? gamma[0] : 0.0f;
    #pragma unroll
    for (int mf = 0; mf < 2; mf++) {
        #pragma unroll
        for (int half = 0; half < 2; half++) {
            const int o = m0 + wM * 32 + mf * 16 + g + half * 8;
            #pragma unroll
            for (int j = 0; j < 4; j++) {
                const int n = n0 + wN * 32 + j * 8 + tq * 2;
                const float v0r = racc[mf][j][half * 2 + 0];
                const float v1r = racc[mf][j][half * 2 + 1];
                if (mode == 0) {
                    const int wi = o >> 8, oc = o & 255;
                    const float* bp = (wi == 0) ? bias0 : (wi == 1) ? bias1 : bias2;
                    const float bia = bp[oc];
                    const float sc = (wi == 0) ? LOG2E : 1.0f;  // q pre-scaled
                    const size_t idx = (((size_t)wi * B_ + b) * C_ + oc) * HW_ + n;
                    __half h0, l0, h1, l1;
                    split1h((v0r + bia) * sc, h0, l0);
                    split1h((v1r + bia) * sc, h1, l1);
                    *(__half2*)&dsth[idx] = __half2(h0, h1);
                    *(__half2*)&dstl[idx] = __half2(l0, l1);
                } else {
                    const float bia = bias0[o];
                    const size_t idx = ((size_t)b * C_ + o) * HW_ + n;
                    const float2 rr = *(const float2*)&resid[idx];
                    float2 r;
                    r.x = gm * (v0r + bia) + rr.x;
                    r.y = gm * (v1r + bia) + rr.y;
                    *(float2*)&dstf[idx] = r;
                }
            }
        }
    }
}

// ===========================================================================
// HMMA flash attention v9: Bc=128, 32-m chunk online softmax, 2-TERM S split
// S = (qh + ql) * kh  — K-lo plane eliminated (MMAs 176->144/iter, -1/3 KV
// traffic, smem 86->68.6KB). ex2.f16x2, L via ones-column MMA.
// 256-query CTA, 8 warps x 32 q, 2 CTAs/SM. S in log2 domain.
// ===========================================================================
#define AQ_OFF 0
#define AQ_ROW 528
#define AQ_PLANE (32 * AQ_ROW)                       // 16896
#define AK_OFF (AQ_OFF + 2 * AQ_PLANE)               // 33792
#define AKV_ROW 272                                  // 128 m * 2B + 16 pad
#define AKV_PLANE (32 * AKV_ROW)                     // 8704
#define AV_OFF (AK_OFF + 2 * AKV_PLANE)              // 51200 (K dbl-buffered)
#define AT_SMEM (AV_OFF + 2 * AKV_PLANE)             // 68608

__global__ __launch_bounds__(256, 2) void attn_mma_kernel(
    const __half* __restrict__ qkvh, const __half* __restrict__ qkvl,
    __nv_bfloat16* __restrict__ oh, __nv_bfloat16* __restrict__ ol)
{
    extern __shared__ char smem[];
    const uint32_t sb = smem_u32(smem);

    const int bh = blockIdx.y;
    const int q0 = blockIdx.x << 8;
    const int t  = threadIdx.x;
    const int w  = t >> 5;
    const int lane = t & 31;
    const int g = lane >> 2, tq = lane & 3;
    const int b = bh >> 3, hh = bh & 7;

    const size_t qoff = (((size_t)0 * B_ + b) * C_ + hh * DH_) * HW_;
    const size_t koff = (((size_t)1 * B_ + b) * C_ + hh * DH_) * HW_;
    const size_t voff = (((size_t)2 * B_ + b) * C_ + hh * DH_) * HW_;
    const __half* qp0 = qkvh + qoff;
    const __half* qp1 = qkvl + qoff;
    const __half* kp  = qkvh + koff;     // K hi only — lo plane unused
    const __half* vp  = qkvh + voff;

    // ---- issue Q (2 planes, 2048 cp16) + KV iter0 (1024 cp16: kh, vh)
    {
        #pragma unroll
        for (int i = 0; i < 8; i++) {
            const int idx = t + (i << 8);
            const int p = idx >> 10;
            const int r = idx & 1023;
            const int d = r >> 5, ch = r & 31;
            const __half* src = (p ? qp1 : qp0) + (size_t)d * HW_ + q0 + ch * 8;
            cp16(sb + AQ_OFF + p * AQ_PLANE + d * AQ_ROW + ch * 16, src);
        }
        #pragma unroll
        for (int i = 0; i < 4; i++) {
            const int idx = t + (i << 8);
            const int p2 = idx >> 9;           // 0 kh, 1 vh
            const int r = idx & 511;
            const int d = r >> 4, ch = r & 15;
            const __half* src = (p2 ? vp : kp) + (size_t)d * HW_ + ch * 8;
            const uint32_t so = p2 ? AV_OFF : AK_OFF;
            cp16(sb + so + d * AKV_ROW + ch * 16, src);
        }
        CP_COMMIT();
    }
    CP_WAIT(0);
    __syncthreads();

    // lane addressing
    const int qrow = (lane & 7) + ((lane >> 4) << 3);
    const int qsel = ((lane >> 3) & 1) << 3;
    const uint32_t qbase = sb + AQ_OFF + qrow * AQ_ROW + (w * 32 + qsel) * 2;
    const int kRowD = (lane & 7) + ((lane >> 4) << 3);
    const int kColB = ((lane >> 3) & 1) * 16;
    const int vRowP = (lane & 7) + (((lane >> 4) & 1) << 3);
    const int vColB = ((lane >> 3) & 1) * 16;

    float oacc[2][4][4] = {};
    float oL[2][4] = {};
    float M0[2] = { -INFINITY, -INFINITY };
    float M1[2] = { -INFINITY, -INFINITY };
    const uint32_t bOnes = (lane < 4) ? 0x3C003C00u : 0u;   // ones in col 0

    for (int i = 0; i < 32; i++) {
        const uint32_t kBuf = (uint32_t)(i & 1) * AKV_PLANE;
        const uint32_t vBuf = (uint32_t)(i & 1) * AKV_PLANE;
        if (i < 31) {
            const int m0n = (i + 1) << 7;
            const uint32_t kBufN = (uint32_t)((i + 1) & 1) * AKV_PLANE;
            const uint32_t vBufN = (uint32_t)((i + 1) & 1) * AKV_PLANE;
            #pragma unroll
            for (int u = 0; u < 4; u++) {
                const int idx = t + (u << 8);
                const int p2 = idx >> 9;
                const int r = idx & 511;
                const int d = r >> 4, ch = r & 15;
                const __half* src = (p2 ? vp : kp) + (size_t)d * HW_ + m0n + ch * 8;
                const uint32_t so = p2 ? (AV_OFF + vBufN) : (AK_OFF + kBufN);
                cp16(sb + so + d * AKV_ROW + ch * 16, src);
            }
            CP_COMMIT();
            CP_WAIT(1);
        } else {
            CP_WAIT(0);
        }
        __syncthreads();

        // ---- four 32-m chunks
        #pragma unroll
        for (int jc = 0; jc < 4; jc++) {
            float sc[2][4][4] = {};   // [mf][nb 0..3][4]
            #pragma unroll
            for (int s = 0; s < 2; s++) {
                uint32_t aQs[2][2][4];   // [plane][mf][4]
                #pragma unroll
                for (int p = 0; p < 2; p++)
                    #pragma unroll
                    for (int mf = 0; mf < 2; mf++)
                        ldsm_x4_t(aQs[p][mf],
                            qbase + p * AQ_PLANE + s * 16 * AQ_ROW + mf * 32);
                #pragma unroll
                for (int jpi = 0; jpi < 2; jpi++) {
                    const int jp = jc * 2 + jpi;
                    uint32_t kh4[4];
                    const uint32_t ka = kBuf + ((s << 4) + kRowD) * AKV_ROW
                                      + jp * 32 + kColB;
                    ldsm_x4_t(kh4, sb + AK_OFF + ka);
                    #pragma unroll
                    for (int mf = 0; mf < 2; mf++) {
                        mma_f16(sc[mf][2*jpi],   aQs[0][mf], kh4[0], kh4[2]);
                        mma_f16(sc[mf][2*jpi+1], aQs[0][mf], kh4[1], kh4[3]);
                        mma_f16(sc[mf][2*jpi],   aQs[1][mf], kh4[0], kh4[2]);
                        mma_f16(sc[mf][2*jpi+1], aQs[1][mf], kh4[1], kh4[3]);
                    }
                }
            }

            // ---- online softmax over this 32-m chunk (log2 domain)
            uint32_t ah[2][2][4];   // [mf][jpi][4] packed fp16 P
            #pragma unroll
            for (int mf = 0; mf < 2; mf++) {
                float c0 = fmaxf(
                    fmaxf(fmaxf(sc[mf][0][0], sc[mf][0][1]),
                          fmaxf(sc[mf][1][0], sc[mf][1][1])),
                    fmaxf(fmaxf(sc[mf][2][0], sc[mf][2][1]),
                          fmaxf(sc[mf][3][0], sc[mf][3][1])));
                float c1 = fmaxf(
                    fmaxf(fmaxf(sc[mf][0][2], sc[mf][0][3]),
                          fmaxf(sc[mf][1][2], sc[mf][1][3])),
                    fmaxf(fmaxf(sc[mf][2][2], sc[mf][2][3]),
                          fmaxf(sc[mf][3][2], sc[mf][3][3])));
                c0 = fmaxf(c0, __shfl_xor_sync(0xffffffffu, c0, 1));
                c0 = fmaxf(c0, __shfl_xor_sync(0xffffffffu, c0, 2));
                c1 = fmaxf(c1, __shfl_xor_sync(0xffffffffu, c1, 1));
                c1 = fmaxf(c1, __shfl_xor_sync(0xffffffffu, c1, 2));

                const float Mn0 = fmaxf(M0[mf], c0);
                const float al0 = fexp2(M0[mf] - Mn0);
                M0[mf] = Mn0;
                const float Mn1 = fmaxf(M1[mf], c1);
                const float al1 = fexp2(M1[mf] - Mn1);
                M1[mf] = Mn1;

                #pragma unroll
                for (int dj = 0; dj < 4; dj++) {
                    oacc[mf][dj][0] *= al0; oacc[mf][dj][1] *= al0;
                    oacc[mf][dj][2] *= al1; oacc[mf][dj][3] *= al1;
                }
                oL[mf][0] *= al0; oL[mf][2] *= al1;

                #pragma unroll
                for (int nb = 0; nb < 4; nb++) {
                    const float t0 = sc[mf][nb][0] - Mn0;
                    const float t1 = sc[mf][nb][1] - Mn0;
                    const float t2 = sc[mf][nb][2] - Mn1;
                    const float t3 = sc[mf][nb][3] - Mn1;
                    ah[mf][nb >> 1][(nb & 1) * 2 + 0] = ex2h2(packh(t0, t1));
                    ah[mf][nb >> 1][(nb & 1) * 2 + 1] = ex2h2(packh(t2, t3));
                }
            }

            // ---- PV + L-column
            #pragma unroll
            for (int jpi = 0; jpi < 2; jpi++) {
                const int jp = jc * 2 + jpi;
                #pragma unroll
                for (int jpd = 0; jpd < 2; jpd++) {
                    uint32_t vh4[4];
                    ldsm_x4(vh4, sb + AV_OFF + vBuf
                                 + (jpd * 16 + vRowP) * AKV_ROW
                                 + jp * 32 + vColB);
                    #pragma unroll
                    for (int mf = 0; mf < 2; mf++) {
                        mma_f16(oacc[mf][2*jpd],   ah[mf][jpi], vh4[0], vh4[1]);
                        mma_f16(oacc[mf][2*jpd+1], ah[mf][jpi], vh4[2], vh4[3]);
                    }
                }
                #pragma unroll
                for (int mf = 0; mf < 2; mf++)
                    mma_f16(oL[mf], ah[mf][jpi], bOnes, bOnes);
            }
        }
        __syncthreads();
    }

    // ---- epilogue: broadcast L from tq==0 lanes, normalize, split, store
    #pragma unroll
    for (int mf = 0; mf < 2; mf++) {
        const float L0 = __shfl_sync(0xffffffffu, oL[mf][0], lane & 28);
        const float L1 = __shfl_sync(0xffffffffu, oL[mf][2], lane & 28);
        const float inv0 = 1.0f / L0;
        const float inv1 = 1.0f / L1;
        #pragma unroll
        for (int h = 0; h < 2; h++) {
            const float inv = h ? inv1 : inv0;
            const int hw = q0 + w * 32 + mf * 16 + g + h * 8;
            #pragma unroll
            for (int dj = 0; dj < 4; dj++) {
                const int d = 8 * dj + tq * 2;
                const float v0 = oacc[mf][dj][h * 2 + 0] * inv;
                const float v1 = oacc[mf][dj][h * 2 + 1] * inv;
                __nv_bfloat16 h0, l0, h1, l1;
                split1(v0, h0, l0); split1(v1, h1, l1);
                const size_t idx = ((size_t)b * HW_ + hw) * C_ + hh * 32 + d;
                *(__nv_bfloat162*)&oh[idx] = __nv_bfloat162(h0, h1);
                *(__nv_bfloat162*)&ol[idx] = __nv_bfloat162(l0, l1);
            }
        }
    }
}

// ===========================================================================
extern "C" void kernel_launch(void* const* d_in, const int* in_sizes, int n_in,
                              void* d_out, int out_size)
{
    const float* x     = (const float*)d_in[0];
    const float* Wq    = (const float*)d_in[1];
    const float* bq    = (const float*)d_in[2];
    const float* Wk    = (const float*)d_in[3];
    const float* bk    = (const float*)d_in[4];
    const float* Wv    = (const float*)d_in[5];
    const float* bv    = (const float*)d_in[6];
    const float* Wo    = (const float*)d_in[7];
    const float* bo    = (const float*)d_in[8];
    const float* gamma = (const float*)d_in[9];
    float* out = (float*)d_out;

    __nv_bfloat16 *xh, *xl, *aoh, *aol, *wh, *wl;
    __half *qkvh, *qkvl;
    cudaGetSymbolAddress((void**)&xh,   g_xh);
    cudaGetSymbolAddress((void**)&xl,   g_xl);
    cudaGetSymbolAddress((void**)&qkvh, g_qkvh);
    cudaGetSymbolAddress((void**)&qkvl, g_qkvl);
    cudaGetSymbolAddress((void**)&aoh,  g_aoh);
    cudaGetSymbolAddress((void**)&aol,  g_aol);
    cudaGetSymbolAddress((void**)&wh,   g_wh);
    cudaGetSymbolAddress((void**)&wl,   g_wl);

    cudaFuncSetAttribute(proj_mma_kernel,
                         cudaFuncAttributeMaxDynamicSharedMemorySize, PJ_SMEM);
    cudaFuncSetAttribute(attn_mma_kernel,
                         cudaFuncAttributeMaxDynamicSharedMemorySize, AT_SMEM);

    wsplit_kernel<<<dim3(256, 4), 256>>>(Wq, Wk, Wv, Wo);
    xsplit_kernel<<<dim3(HW_ / 32, C_ / 32, B_), dim3(32, 8)>>>(x);

    // fused QKV projection: M = 768
    proj_mma_kernel<<<dim3(HW_ / 128, 6, B_), 512, PJ_SMEM>>>(
        wh, wl, bq, bk, bv, xh, xl, qkvh, qkvl, nullptr, nullptr, nullptr, 0);

    attn_mma_kernel<<<dim3(HW_ / 256, B_ * NH_), 256, AT_SMEM>>>(
        qkvh, qkvl, aoh, aol);

    // output projection: W rows 768..1023
    proj_mma_kernel<<<dim3(HW_ / 128, 2, B_), 512, PJ_SMEM>>>(
        wh + 3 * C_ * C_, wl + 3 * C_ * C_, bo, nullptr, nullptr,
        aoh, aol, nullptr, nullptr, out, x, gamma, 1);
}

// round 16
// speedup vs baseline: 1.4762x; 1.2795x over previous
#include <cuda_runtime.h>
#include <cuda_bf16.h>
#include <cuda_fp16.h>
#include <math.h>
#include <stdint.h>

#define C_   256
#define HW_  4096
#define B_   2
#define NH_  8
#define DH_  32
#define LOG2E 1.4426950408889634f

// ---------------------------------------------------------------------------
// Scratch:
//   g_xh/g_xl   : x transposed+split  [b][hw][c]            bf16
//   g_qkv       : q,k,v fp16 planes   [wi][b][c][hw]        (q pre-scaled by LOG2E)
//   g_aoh/g_aol : attention out       [b][hw][c]            bf16
//   g_wh/g_wl   : stacked weights     [wi][o][c] (wi: q,k,v,o)  bf16
// ---------------------------------------------------------------------------
__device__ __nv_bfloat16 g_xh[B_ * HW_ * C_];
__device__ __nv_bfloat16 g_xl[B_ * HW_ * C_];
__device__ __half        g_qkv[3 * B_ * C_ * HW_];
__device__ __nv_bfloat16 g_aoh[B_ * HW_ * C_];
__device__ __nv_bfloat16 g_aol[B_ * HW_ * C_];
__device__ __nv_bfloat16 g_wh[4 * C_ * C_];
__device__ __nv_bfloat16 g_wl[4 * C_ * C_];

// ===========================================================================
// helpers
// ===========================================================================
__device__ __forceinline__ uint32_t smem_u32(const void* p) {
    uint32_t a;
    asm("{ .reg .u64 t; cvta.to.shared.u64 t, %1; cvt.u32.u64 %0, t; }"
        : "=r"(a) : "l"(p));
    return a;
}
__device__ __forceinline__ void cp16(uint32_t saddr, const void* gaddr) {
    asm volatile("cp.async.cg.shared.global [%0], [%1], 16;"
                 :: "r"(saddr), "l"(gaddr));
}
#define CP_COMMIT() asm volatile("cp.async.commit_group;")
#define CP_WAIT(N)  asm volatile("cp.async.wait_group %0;" :: "n"(N))

__device__ __forceinline__ void ldsm_x4(uint32_t a[4], uint32_t addr) {
    asm volatile("ldmatrix.sync.aligned.m8n8.x4.shared.b16 {%0,%1,%2,%3}, [%4];"
                 : "=r"(a[0]), "=r"(a[1]), "=r"(a[2]), "=r"(a[3]) : "r"(addr));
}
__device__ __forceinline__ void ldsm_x4_t(uint32_t a[4], uint32_t addr) {
    asm volatile("ldmatrix.sync.aligned.m8n8.x4.trans.shared.b16 {%0,%1,%2,%3}, [%4];"
                 : "=r"(a[0]), "=r"(a[1]), "=r"(a[2]), "=r"(a[3]) : "r"(addr));
}
__device__ __forceinline__ void mma_bf16(float c[4], const uint32_t a[4],
                                         uint32_t b0, uint32_t b1) {
    asm volatile("mma.sync.aligned.m16n8k16.row.col.f32.bf16.bf16.f32 "
                 "{%0,%1,%2,%3}, {%4,%5,%6,%7}, {%8,%9}, {%0,%1,%2,%3};"
                 : "+f"(c[0]), "+f"(c[1]), "+f"(c[2]), "+f"(c[3])
                 : "r"(a[0]), "r"(a[1]), "r"(a[2]), "r"(a[3]), "r"(b0), "r"(b1));
}
__device__ __forceinline__ void mma_f16(float c[4], const uint32_t a[4],
                                        uint32_t b0, uint32_t b1) {
    asm volatile("mma.sync.aligned.m16n8k16.row.col.f32.f16.f16.f32 "
                 "{%0,%1,%2,%3}, {%4,%5,%6,%7}, {%8,%9}, {%0,%1,%2,%3};"
                 : "+f"(c[0]), "+f"(c[1]), "+f"(c[2]), "+f"(c[3])
                 : "r"(a[0]), "r"(a[1]), "r"(a[2]), "r"(a[3]), "r"(b0), "r"(b1));
}
__device__ __forceinline__ float fexp2(float x) {
    float y; asm("ex2.approx.f32 %0, %1;" : "=f"(y) : "f"(x)); return y;
}
// packed fp16x2 exp2
__device__ __forceinline__ uint32_t ex2h2(uint32_t a) {
    uint32_t d; asm("ex2.approx.f16x2 %0, %1;" : "=r"(d) : "r"(a)); return d;
}
// pack (lo element, hi element) -> f16x2 (first arg in low 16 bits)
__device__ __forceinline__ uint32_t packh(float lo, float hi) {
    uint32_t u; asm("cvt.rn.f16x2.f32 %0, %1, %2;" : "=r"(u) : "f"(hi), "f"(lo));
    return u;
}
__device__ __forceinline__ void split1(float f, __nv_bfloat16& h, __nv_bfloat16& l) {
    h = __float2bfloat16_rn(f);
    l = __float2bfloat16_rn(f - __bfloat162float(h));
}

// ===========================================================================
// Weight split: 4 x [256x256] fp32 -> stacked bf16 hi/lo [1024][256]
// ===========================================================================
__global__ __launch_bounds__(256) void wsplit_kernel(
    const float* __restrict__ W0, const float* __restrict__ W1,
    const float* __restrict__ W2, const float* __restrict__ W3)
{
    const int wi = blockIdx.y;
    const float* W = (wi == 0) ? W0 : (wi == 1) ? W1 : (wi == 2) ? W2 : W3;
    const int idx = blockIdx.x * 256 + threadIdx.x;
    __nv_bfloat16 h, l;
    split1(W[idx], h, l);
    g_wh[wi * C_ * C_ + idx] = h;
    g_wl[wi * C_ * C_ + idx] = l;
}

// ===========================================================================
// x transpose+split: [b][c][hw] fp32 -> [b][hw][c] bf16 hi/lo
// ===========================================================================
__global__ __launch_bounds__(256) void xsplit_kernel(const float* __restrict__ x)
{
    __shared__ float tile[32][33];
    const int hw0 = blockIdx.x << 5;
    const int c0  = blockIdx.y << 5;
    const int b   = blockIdx.z;
    const int tx = threadIdx.x, ty = threadIdx.y;   // (32, 8)
    #pragma unroll
    for (int yy = 0; yy < 4; yy++)
        tile[ty + 8 * yy][tx] =
            x[((size_t)b * C_ + c0 + ty + 8 * yy) * HW_ + hw0 + tx];
    __syncthreads();
    #pragma unroll
    for (int yy = 0; yy < 4; yy++) {
        const int hw = hw0 + ty + 8 * yy;
        const int c  = c0 + tx;
        __nv_bfloat16 h, l;
        split1(tile[tx][ty + 8 * yy], h, l);
        g_xh[((size_t)b * HW_ + hw) * C_ + c] = h;
        g_xl[((size_t)b * HW_ + hw) * C_ + c] = l;
    }
}

// ===========================================================================
// Tensor-core projection. 512 threads, 16 warps (4 oM x 4 nN), tile 128x128,
// warp tile 32x32. A = W bf16 planes [o][c], B = X bf16 planes [n][c].
//   mode 0 (qkv): o in 0..767, write single fp16 to [wi][b][oc][hw]
//                 (q rows pre-scaled by LOG2E)
//   mode 1 (out): o in 0..255, write fp32 gamma*(acc+bias)+resid
// ===========================================================================
#define PJ_PLANE 10240          // 128 rows x 80B
#define PJ_BUF   40960          // 4 planes
#define PJ_SMEM  81920

__global__ __launch_bounds__(512) void proj_mma_kernel(
    const __nv_bfloat16* __restrict__ Wh, const __nv_bfloat16* __restrict__ Wl,
    const float* __restrict__ bias0, const float* __restrict__ bias1,
    const float* __restrict__ bias2,
    const __nv_bfloat16* __restrict__ Xh, const __nv_bfloat16* __restrict__ Xl,
    __half* __restrict__ dsth,
    float* __restrict__ dstf, const float* __restrict__ resid,
    const float* __restrict__ gamma, int mode)
{
    extern __shared__ char smem[];
    const uint32_t sb = smem_u32(smem);

    const int n0 = blockIdx.x << 7;
    const int m0 = blockIdx.y << 7;
    const int b  = blockIdx.z;
    const int t  = threadIdx.x;
    const int w  = t >> 5, lane = t & 31;
    const int wM = w & 3, wN = w >> 2;
    const int g = lane >> 2, tq = lane & 3;

    // 2048 cp16 per buffer, 4 per thread
    auto load_buf = [&](int kc, uint32_t bufo) {
        #pragma unroll
        for (int i = 0; i < 4; i++) {
            const int idx = t + (i << 9);
            const int p = idx >> 9;
            const int r = idx & 511;
            const int row = r >> 2, ch = r & 3;
            const __nv_bfloat16* src;
            if (p < 2) src = (p ? Wl : Wh) + (size_t)(m0 + row) * C_ + kc * 32 + ch * 8;
            else       src = (p == 3 ? Xl : Xh)
                           + ((size_t)b * HW_ + n0 + row) * C_ + kc * 32 + ch * 8;
            cp16(sb + bufo + p * PJ_PLANE + row * 80 + ch * 16, src);
        }
        CP_COMMIT();
    };

    load_buf(0, 0);

    float racc[2][4][4] = {};

    const int arow = (lane & 7) + ((lane >> 3) & 1) * 8;
    const int acol = ((lane >> 4) & 1) * 16;            // k-half bytes
    const int brow = (lane & 7);
    const int bsel8  = ((lane >> 3) & 1) * 16;          // k-half bytes
    const int bsel16 = ((lane >> 4) & 1) * 8;           // n +8 rows

    for (int kc = 0; kc < 8; kc++) {
        const uint32_t bufC = (uint32_t)(kc & 1) * PJ_BUF;
        if (kc < 7) load_buf(kc + 1, (uint32_t)((kc + 1) & 1) * PJ_BUF);
        if (kc < 7) { CP_WAIT(1); } else { CP_WAIT(0); }
        __syncthreads();

        #pragma unroll
        for (int kk = 0; kk < 2; kk++) {
            uint32_t aW[2][2][4];   // [plane][mf][4]
            #pragma unroll
            for (int p = 0; p < 2; p++)
                #pragma unroll
                for (int mf = 0; mf < 2; mf++)
                    ldsm_x4(aW[p][mf],
                        sb + bufC + p * PJ_PLANE
                           + (wM * 32 + mf * 16 + arow) * 80 + kk * 32 + acol);

            #pragma unroll
            for (int jp = 0; jp < 2; jp++) {
                uint32_t bh4[4], bl4[4];
                const uint32_t baddr = (wN * 32 + jp * 16 + bsel16 + brow) * 80
                                     + kk * 32 + bsel8;
                ldsm_x4(bh4, sb + bufC + 2 * PJ_PLANE + baddr);
                ldsm_x4(bl4, sb + bufC + 3 * PJ_PLANE + baddr);
                #pragma unroll
                for (int mf = 0; mf < 2; mf++) {
                    mma_bf16(racc[mf][2*jp],   aW[0][mf], bh4[0], bh4[1]);
                    mma_bf16(racc[mf][2*jp+1], aW[0][mf], bh4[2], bh4[3]);
                    mma_bf16(racc[mf][2*jp],   aW[1][mf], bh4[0], bh4[1]);
                    mma_bf16(racc[mf][2*jp+1], aW[1][mf], bh4[2], bh4[3]);
                    mma_bf16(racc[mf][2*jp],   aW[0][mf], bl4[0], bl4[1]);
                    mma_bf16(racc[mf][2*jp+1], aW[0][mf], bl4[2], bl4[3]);
                }
            }
        }
        __syncthreads();
    }

    // epilogue
    const float gm = (mode == 1) ? gamma[0] : 0.0f;
    #pragma unroll
    for (int mf = 0; mf < 2; mf++) {
        #pragma unroll
        for (int half = 0; half < 2; half++) {
            const int o = m0 + wM * 32 + mf * 16 + g + half * 8;
            #pragma unroll
            for (int j = 0; j < 4; j++) {
                const int n = n0 + wN * 32 + j * 8 + tq * 2;
                const float v0r = racc[mf][j][half * 2 + 0];
                const float v1r = racc[mf][j][half * 2 + 1];
                if (mode == 0) {
                    const int wi = o >> 8, oc = o & 255;
                    const float* bp = (wi == 0) ? bias0 : (wi == 1) ? bias1 : bias2;
                    const float bia = bp[oc];
                    const float sc = (wi == 0) ? LOG2E : 1.0f;  // q pre-scaled
                    const size_t idx = (((size_t)wi * B_ + b) * C_ + oc) * HW_ + n;
                    const __half h0 = __float2half_rn((v0r + bia) * sc);
                    const __half h1 = __float2half_rn((v1r + bia) * sc);
                    *(__half2*)&dsth[idx] = __half2(h0, h1);
                } else {
                    const float bia = bias0[o];
                    const size_t idx = ((size_t)b * C_ + o) * HW_ + n;
                    const float2 rr = *(const float2*)&resid[idx];
                    float2 r;
                    r.x = gm * (v0r + bia) + rr.x;
                    r.y = gm * (v1r + bia) + rr.y;
                    *(float2*)&dstf[idx] = r;
                }
            }
        }
    }
}

// ===========================================================================
// HMMA flash attention v10: pure fp16 S = qh*kh (single term), Bc=128,
// 32-m chunk online softmax, ex2.f16x2, L via ones-column MMA.
// 256-query CTA, 8 warps x 32 q, 2 CTAs/SM. S in log2 domain.
// ===========================================================================
#define AQ_OFF 0
#define AQ_ROW 528
#define AQ_PLANE (32 * AQ_ROW)                       // 16896 (single plane)
#define AK_OFF AQ_PLANE                              // 16896
#define AKV_ROW 272                                  // 128 m * 2B + 16 pad
#define AKV_PLANE (32 * AKV_ROW)                     // 8704
#define AV_OFF (AK_OFF + 2 * AKV_PLANE)              // 34304 (K dbl-buffered)
#define AT_SMEM (AV_OFF + 2 * AKV_PLANE)             // 51712

__global__ __launch_bounds__(256, 2) void attn_mma_kernel(
    const __half* __restrict__ qkv,
    __nv_bfloat16* __restrict__ oh, __nv_bfloat16* __restrict__ ol)
{
    extern __shared__ char smem[];
    const uint32_t sb = smem_u32(smem);

    const int bh = blockIdx.y;
    const int q0 = blockIdx.x << 8;
    const int t  = threadIdx.x;
    const int w  = t >> 5;
    const int lane = t & 31;
    const int g = lane >> 2, tq = lane & 3;
    const int b = bh >> 3, hh = bh & 7;

    const size_t qoff = (((size_t)0 * B_ + b) * C_ + hh * DH_) * HW_;
    const size_t koff = (((size_t)1 * B_ + b) * C_ + hh * DH_) * HW_;
    const size_t voff = (((size_t)2 * B_ + b) * C_ + hh * DH_) * HW_;
    const __half* qp = qkv + qoff;
    const __half* kp = qkv + koff;
    const __half* vp = qkv + voff;

    // ---- issue Q (1024 cp16) + KV iter0 (1024 cp16: kh, vh)
    {
        #pragma unroll
        for (int i = 0; i < 4; i++) {
            const int idx = t + (i << 8);            // 0..1023
            const int d = idx >> 5, ch = idx & 31;
            cp16(sb + AQ_OFF + d * AQ_ROW + ch * 16,
                 qp + (size_t)d * HW_ + q0 + ch * 8);
        }
        #pragma unroll
        for (int i = 0; i < 4; i++) {
            const int idx = t + (i << 8);
            const int p2 = idx >> 9;           // 0 kh, 1 vh
            const int r = idx & 511;
            const int d = r >> 4, ch = r & 15;
            const __half* src = (p2 ? vp : kp) + (size_t)d * HW_ + ch * 8;
            const uint32_t so = p2 ? AV_OFF : AK_OFF;
            cp16(sb + so + d * AKV_ROW + ch * 16, src);
        }
        CP_COMMIT();
    }
    CP_WAIT(0);
    __syncthreads();

    // lane addressing
    const int qrow = (lane & 7) + ((lane >> 4) << 3);
    const int qsel = ((lane >> 3) & 1) << 3;
    const uint32_t qbase = sb + AQ_OFF + qrow * AQ_ROW + (w * 32 + qsel) * 2;
    const int kRowD = (lane & 7) + ((lane >> 4) << 3);
    const int kColB = ((lane >> 3) & 1) * 16;
    const int vRowP = (lane & 7) + (((lane >> 4) & 1) << 3);
    const int vColB = ((lane >> 3) & 1) * 16;

    float oacc[2][4][4] = {};
    float oL[2][4] = {};
    float M0[2] = { -INFINITY, -INFINITY };
    float M1[2] = { -INFINITY, -INFINITY };
    const uint32_t bOnes = (lane < 4) ? 0x3C003C00u : 0u;   // ones in col 0

    for (int i = 0; i < 32; i++) {
        const uint32_t kBuf = (uint32_t)(i & 1) * AKV_PLANE;
        const uint32_t vBuf = (uint32_t)(i & 1) * AKV_PLANE;
        if (i < 31) {
            const int m0n = (i + 1) << 7;
            const uint32_t kBufN = (uint32_t)((i + 1) & 1) * AKV_PLANE;
            const uint32_t vBufN = (uint32_t)((i + 1) & 1) * AKV_PLANE;
            #pragma unroll
            for (int u = 0; u < 4; u++) {
                const int idx = t + (u << 8);
                const int p2 = idx >> 9;
                const int r = idx & 511;
                const int d = r >> 4, ch = r & 15;
                const __half* src = (p2 ? vp : kp) + (size_t)d * HW_ + m0n + ch * 8;
                const uint32_t so = p2 ? (AV_OFF + vBufN) : (AK_OFF + kBufN);
                cp16(sb + so + d * AKV_ROW + ch * 16, src);
            }
            CP_COMMIT();
            CP_WAIT(1);
        } else {
            CP_WAIT(0);
        }
        __syncthreads();

        // ---- four 32-m chunks
        #pragma unroll
        for (int jc = 0; jc < 4; jc++) {
            float sc[2][4][4] = {};   // [mf][nb 0..3][4]
            #pragma unroll
            for (int s = 0; s < 2; s++) {
                uint32_t aQs[2][4];   // [mf][4]
                #pragma unroll
                for (int mf = 0; mf < 2; mf++)
                    ldsm_x4_t(aQs[mf],
                        qbase + s * 16 * AQ_ROW + mf * 32);
                #pragma unroll
                for (int jpi = 0; jpi < 2; jpi++) {
                    const int jp = jc * 2 + jpi;
                    uint32_t kh4[4];
                    const uint32_t ka = kBuf + ((s << 4) + kRowD) * AKV_ROW
                                      + jp * 32 + kColB;
                    ldsm_x4_t(kh4, sb + AK_OFF + ka);
                    #pragma unroll
                    for (int mf = 0; mf < 2; mf++) {
                        mma_f16(sc[mf][2*jpi],   aQs[mf], kh4[0], kh4[2]);
                        mma_f16(sc[mf][2*jpi+1], aQs[mf], kh4[1], kh4[3]);
                    }
                }
            }

            // ---- online softmax over this 32-m chunk (log2 domain)
            uint32_t ah[2][2][4];   // [mf][jpi][4] packed fp16 P
            #pragma unroll
            for (int mf = 0; mf < 2; mf++) {
                float c0 = fmaxf(
                    fmaxf(fmaxf(sc[mf][0][0], sc[mf][0][1]),
                          fmaxf(sc[mf][1][0], sc[mf][1][1])),
                    fmaxf(fmaxf(sc[mf][2][0], sc[mf][2][1]),
                          fmaxf(sc[mf][3][0], sc[mf][3][1])));
                float c1 = fmaxf(
                    fmaxf(fmaxf(sc[mf][0][2], sc[mf][0][3]),
                          fmaxf(sc[mf][1][2], sc[mf][1][3])),
                    fmaxf(fmaxf(sc[mf][2][2], sc[mf][2][3]),
                          fmaxf(sc[mf][3][2], sc[mf][3][3])));
                c0 = fmaxf(c0, __shfl_xor_sync(0xffffffffu, c0, 1));
                c0 = fmaxf(c0, __shfl_xor_sync(0xffffffffu, c0, 2));
                c1 = fmaxf(c1, __shfl_xor_sync(0xffffffffu, c1, 1));
                c1 = fmaxf(c1, __shfl_xor_sync(0xffffffffu, c1, 2));

                const float Mn0 = fmaxf(M0[mf], c0);
                const float al0 = fexp2(M0[mf] - Mn0);
                M0[mf] = Mn0;
                const float Mn1 = fmaxf(M1[mf], c1);
                const float al1 = fexp2(M1[mf] - Mn1);
                M1[mf] = Mn1;

                #pragma unroll
                for (int dj = 0; dj < 4; dj++) {
                    oacc[mf][dj][0] *= al0; oacc[mf][dj][1] *= al0;
                    oacc[mf][dj][2] *= al1; oacc[mf][dj][3] *= al1;
                }
                oL[mf][0] *= al0; oL[mf][2] *= al1;

                #pragma unroll
                for (int nb = 0; nb < 4; nb++) {
                    const float t0 = sc[mf][nb][0] - Mn0;
                    const float t1 = sc[mf][nb][1] - Mn0;
                    const float t2 = sc[mf][nb][2] - Mn1;
                    const float t3 = sc[mf][nb][3] - Mn1;
                    ah[mf][nb >> 1][(nb & 1) * 2 + 0] = ex2h2(packh(t0, t1));
                    ah[mf][nb >> 1][(nb & 1) * 2 + 1] = ex2h2(packh(t2, t3));
                }
            }

            // ---- PV + L-column
            #pragma unroll
            for (int jpi = 0; jpi < 2; jpi++) {
                const int jp = jc * 2 + jpi;
                #pragma unroll
                for (int jpd = 0; jpd < 2; jpd++) {
                    uint32_t vh4[4];
                    ldsm_x4(vh4, sb + AV_OFF + vBuf
                                 + (jpd * 16 + vRowP) * AKV_ROW
                                 + jp * 32 + vColB);
                    #pragma unroll
                    for (int mf = 0; mf < 2; mf++) {
                        mma_f16(oacc[mf][2*jpd],   ah[mf][jpi], vh4[0], vh4[1]);
                        mma_f16(oacc[mf][2*jpd+1], ah[mf][jpi], vh4[2], vh4[3]);
                    }
                }
                #pragma unroll
                for (int mf = 0; mf < 2; mf++)
                    mma_f16(oL[mf], ah[mf][jpi], bOnes, bOnes);
            }
        }
        __syncthreads();
    }

    // ---- epilogue: broadcast L from tq==0 lanes, normalize, split, store
    #pragma unroll
    for (int mf = 0; mf < 2; mf++) {
        const float L0 = __shfl_sync(0xffffffffu, oL[mf][0], lane & 28);
        const float L1 = __shfl_sync(0xffffffffu, oL[mf][2], lane & 28);
        const float inv0 = 1.0f / L0;
        const float inv1 = 1.0f / L1;
        #pragma unroll
        for (int h = 0; h < 2; h++) {
            const float inv = h ? inv1 : inv0;
            const int hw = q0 + w * 32 + mf * 16 + g + h * 8;
            #pragma unroll
            for (int dj = 0; dj < 4; dj++) {
                const int d = 8 * dj + tq * 2;
                const float v0 = oacc[mf][dj][h * 2 + 0] * inv;
                const float v1 = oacc[mf][dj][h * 2 + 1] * inv;
                __nv_bfloat16 h0, l0, h1, l1;
                split1(v0, h0, l0); split1(v1, h1, l1);
                const size_t idx = ((size_t)b * HW_ + hw) * C_ + hh * 32 + d;
                *(__nv_bfloat162*)&oh[idx] = __nv_bfloat162(h0, h1);
                *(__nv_bfloat162*)&ol[idx] = __nv_bfloat162(l0, l1);
            }
        }
    }
}

// ===========================================================================
extern "C" void kernel_launch(void* const* d_in, const int* in_sizes, int n_in,
                              void* d_out, int out_size)
{
    const float* x     = (const float*)d_in[0];
    const float* Wq    = (const float*)d_in[1];
    const float* bq    = (const float*)d_in[2];
    const float* Wk    = (const float*)d_in[3];
    const float* bk    = (const float*)d_in[4];
    const float* Wv    = (const float*)d_in[5];
    const float* bv    = (const float*)d_in[6];
    const float* Wo    = (const float*)d_in[7];
    const float* bo    = (const float*)d_in[8];
    const float* gamma = (const float*)d_in[9];
    float* out = (float*)d_out;

    __nv_bfloat16 *xh, *xl, *aoh, *aol, *wh, *wl;
    __half *qkv;
    cudaGetSymbolAddress((void**)&xh,  g_xh);
    cudaGetSymbolAddress((void**)&xl,  g_xl);
    cudaGetSymbolAddress((void**)&qkv, g_qkv);
    cudaGetSymbolAddress((void**)&aoh, g_aoh);
    cudaGetSymbolAddress((void**)&aol, g_aol);
    cudaGetSymbolAddress((void**)&wh,  g_wh);
    cudaGetSymbolAddress((void**)&wl,  g_wl);

    cudaFuncSetAttribute(proj_mma_kernel,
                         cudaFuncAttributeMaxDynamicSharedMemorySize, PJ_SMEM);
    cudaFuncSetAttribute(attn_mma_kernel,
                         cudaFuncAttributeMaxDynamicSharedMemorySize, AT_SMEM);

    wsplit_kernel<<<dim3(256, 4), 256>>>(Wq, Wk, Wv, Wo);
    xsplit_kernel<<<dim3(HW_ / 32, C_ / 32, B_), dim3(32, 8)>>>(x);

    // fused QKV projection: M = 768
    proj_mma_kernel<<<dim3(HW_ / 128, 6, B_), 512, PJ_SMEM>>>(
        wh, wl, bq, bk, bv, xh, xl, qkv, nullptr, nullptr, nullptr, 0);

    attn_mma_kernel<<<dim3(HW_ / 256, B_ * NH_), 256, AT_SMEM>>>(
        qkv, aoh, aol);

    // output projection: W rows 768..1023
    proj_mma_kernel<<<dim3(HW_ / 128, 2, B_), 512, PJ_SMEM>>>(
        wh + 3 * C_ * C_, wl + 3 * C_ * C_, bo, nullptr, nullptr,
        aoh, aol, nullptr, out, x, gamma, 1);
}

// round 17
// speedup vs baseline: 1.5542x; 1.0528x over previous
#include <cuda_runtime.h>
#include <cuda_bf16.h>
#include <cuda_fp16.h>
#include <math.h>
#include <stdint.h>

#define C_   256
#define HW_  4096
#define B_   2
#define NH_  8
#define DH_  32
#define LOG2E 1.4426950408889634f

// ---------------------------------------------------------------------------
// Scratch:
//   g_xf        : x transposed        [b][hw][c]            fp16
//   g_qkv       : q,k,v fp16 planes   [wi][b][c][hw]        (q pre-scaled by LOG2E)
//   g_aoh/g_aol : attention out       [b][hw][c]            bf16 hi/lo
//   g_wfh/g_wfl : Wq,Wk,Wv fp16 hi/lo [wi][o][c]
//   g_wo_h/_l   : Wo bf16 hi/lo       [o][c]
// ---------------------------------------------------------------------------
__device__ __half        g_xf[B_ * HW_ * C_];
__device__ __half        g_qkv[3 * B_ * C_ * HW_];
__device__ __nv_bfloat16 g_aoh[B_ * HW_ * C_];
__device__ __nv_bfloat16 g_aol[B_ * HW_ * C_];
__device__ __half        g_wfh[3 * C_ * C_];
__device__ __half        g_wfl[3 * C_ * C_];
__device__ __nv_bfloat16 g_wo_h[C_ * C_];
__device__ __nv_bfloat16 g_wo_l[C_ * C_];

// ===========================================================================
// helpers
// ===========================================================================
__device__ __forceinline__ uint32_t smem_u32(const void* p) {
    uint32_t a;
    asm("{ .reg .u64 t; cvta.to.shared.u64 t, %1; cvt.u32.u64 %0, t; }"
        : "=r"(a) : "l"(p));
    return a;
}
__device__ __forceinline__ void cp16(uint32_t saddr, const void* gaddr) {
    asm volatile("cp.async.cg.shared.global [%0], [%1], 16;"
                 :: "r"(saddr), "l"(gaddr));
}
#define CP_COMMIT() asm volatile("cp.async.commit_group;")
#define CP_WAIT(N)  asm volatile("cp.async.wait_group %0;" :: "n"(N))

__device__ __forceinline__ void ldsm_x4(uint32_t a[4], uint32_t addr) {
    asm volatile("ldmatrix.sync.aligned.m8n8.x4.shared.b16 {%0,%1,%2,%3}, [%4];"
                 : "=r"(a[0]), "=r"(a[1]), "=r"(a[2]), "=r"(a[3]) : "r"(addr));
}
__device__ __forceinline__ void ldsm_x4_t(uint32_t a[4], uint32_t addr) {
    asm volatile("ldmatrix.sync.aligned.m8n8.x4.trans.shared.b16 {%0,%1,%2,%3}, [%4];"
                 : "=r"(a[0]), "=r"(a[1]), "=r"(a[2]), "=r"(a[3]) : "r"(addr));
}
__device__ __forceinline__ void mma_bf16(float c[4], const uint32_t a[4],
                                         uint32_t b0, uint32_t b1) {
    asm volatile("mma.sync.aligned.m16n8k16.row.col.f32.bf16.bf16.f32 "
                 "{%0,%1,%2,%3}, {%4,%5,%6,%7}, {%8,%9}, {%0,%1,%2,%3};"
                 : "+f"(c[0]), "+f"(c[1]), "+f"(c[2]), "+f"(c[3])
                 : "r"(a[0]), "r"(a[1]), "r"(a[2]), "r"(a[3]), "r"(b0), "r"(b1));
}
__device__ __forceinline__ void mma_f16(float c[4], const uint32_t a[4],
                                        uint32_t b0, uint32_t b1) {
    asm volatile("mma.sync.aligned.m16n8k16.row.col.f32.f16.f16.f32 "
                 "{%0,%1,%2,%3}, {%4,%5,%6,%7}, {%8,%9}, {%0,%1,%2,%3};"
                 : "+f"(c[0]), "+f"(c[1]), "+f"(c[2]), "+f"(c[3])
                 : "r"(a[0]), "r"(a[1]), "r"(a[2]), "r"(a[3]), "r"(b0), "r"(b1));
}
__device__ __forceinline__ float fexp2(float x) {
    float y; asm("ex2.approx.f32 %0, %1;" : "=f"(y) : "f"(x)); return y;
}
// packed fp16x2 exp2
__device__ __forceinline__ uint32_t ex2h2(uint32_t a) {
    uint32_t d; asm("ex2.approx.f16x2 %0, %1;" : "=r"(d) : "r"(a)); return d;
}
// pack (lo element, hi element) -> f16x2 (first arg in low 16 bits)
__device__ __forceinline__ uint32_t packh(float lo, float hi) {
    uint32_t u; asm("cvt.rn.f16x2.f32 %0, %1, %2;" : "=r"(u) : "f"(hi), "f"(lo));
    return u;
}
__device__ __forceinline__ void split1(float f, __nv_bfloat16& h, __nv_bfloat16& l) {
    h = __float2bfloat16_rn(f);
    l = __float2bfloat16_rn(f - __bfloat162float(h));
}

// ===========================================================================
// Weight split: Wq/Wk/Wv -> fp16 hi/lo; Wo -> bf16 hi/lo
// ===========================================================================
__global__ __launch_bounds__(256) void wsplit_kernel(
    const float* __restrict__ W0, const float* __restrict__ W1,
    const float* __restrict__ W2, const float* __restrict__ W3)
{
    const int wi = blockIdx.y;
    const float* W = (wi == 0) ? W0 : (wi == 1) ? W1 : (wi == 2) ? W2 : W3;
    const int idx = blockIdx.x * 256 + threadIdx.x;
    const float v = W[idx];
    if (wi < 3) {
        const __half h = __float2half_rn(v);
        const __half l = __float2half_rn(v - __half2float(h));
        g_wfh[wi * C_ * C_ + idx] = h;
        g_wfl[wi * C_ * C_ + idx] = l;
    } else {
        __nv_bfloat16 h, l;
        split1(v, h, l);
        g_wo_h[idx] = h;
        g_wo_l[idx] = l;
    }
}

// ===========================================================================
// x transpose + cvt: [b][c][hw] fp32 -> [b][hw][c] fp16
// ===========================================================================
__global__ __launch_bounds__(256) void xcvt_kernel(const float* __restrict__ x)
{
    __shared__ float tile[32][33];
    const int hw0 = blockIdx.x << 5;
    const int c0  = blockIdx.y << 5;
    const int b   = blockIdx.z;
    const int tx = threadIdx.x, ty = threadIdx.y;   // (32, 8)
    #pragma unroll
    for (int yy = 0; yy < 4; yy++)
        tile[ty + 8 * yy][tx] =
            x[((size_t)b * C_ + c0 + ty + 8 * yy) * HW_ + hw0 + tx];
    __syncthreads();
    #pragma unroll
    for (int yy = 0; yy < 4; yy++) {
        const int hw = hw0 + ty + 8 * yy;
        const int c  = c0 + tx;
        g_xf[((size_t)b * HW_ + hw) * C_ + c] =
            __float2half_rn(tile[tx][ty + 8 * yy]);
    }
}

// ===========================================================================
// QKV projection: 2-term fp16 (Wh + Wl) * Xf. 512 threads, 16 warps
// (4 oM x 4 nN), tile 128x128, warp tile 32x32. o in 0..767.
// Writes fp16 to [wi][b][oc][hw], q rows pre-scaled by LOG2E.
// ===========================================================================
#define PQ_PLANE 10240          // 128 rows x 80B
#define PQ_BUF   30720          // 3 planes (Wh, Wl, X)
#define PQ_SMEM  61440

__global__ __launch_bounds__(512) void qkvproj_kernel(
    const float* __restrict__ bias0, const float* __restrict__ bias1,
    const float* __restrict__ bias2)
{
    extern __shared__ char smem[];
    const uint32_t sb = smem_u32(smem);

    const int n0 = blockIdx.x << 7;
    const int m0 = blockIdx.y << 7;
    const int b  = blockIdx.z;
    const int t  = threadIdx.x;
    const int w  = t >> 5, lane = t & 31;
    const int wM = w & 3, wN = w >> 2;
    const int g = lane >> 2, tq = lane & 3;

    // 1536 cp16 per buffer, 3 per thread
    auto load_buf = [&](int kc, uint32_t bufo) {
        #pragma unroll
        for (int i = 0; i < 3; i++) {
            const int idx = t + (i << 9);
            const int p = idx >> 9;              // 0 Wh, 1 Wl, 2 X
            const int r = idx & 511;
            const int row = r >> 2, ch = r & 3;
            const __half* src;
            if (p < 2) src = (p ? g_wfl : g_wfh)
                           + (size_t)(m0 + row) * C_ + kc * 32 + ch * 8;
            else       src = g_xf + ((size_t)b * HW_ + n0 + row) * C_
                           + kc * 32 + ch * 8;
            cp16(sb + bufo + p * PQ_PLANE + row * 80 + ch * 16, src);
        }
        CP_COMMIT();
    };

    load_buf(0, 0);

    float racc[2][4][4] = {};

    const int arow = (lane & 7) + ((lane >> 3) & 1) * 8;
    const int acol = ((lane >> 4) & 1) * 16;            // k-half bytes
    const int brow = (lane & 7);
    const int bsel8  = ((lane >> 3) & 1) * 16;          // k-half bytes
    const int bsel16 = ((lane >> 4) & 1) * 8;           // n +8 rows

    for (int kc = 0; kc < 8; kc++) {
        const uint32_t bufC = (uint32_t)(kc & 1) * PQ_BUF;
        if (kc < 7) load_buf(kc + 1, (uint32_t)((kc + 1) & 1) * PQ_BUF);
        if (kc < 7) { CP_WAIT(1); } else { CP_WAIT(0); }
        __syncthreads();

        #pragma unroll
        for (int kk = 0; kk < 2; kk++) {
            uint32_t aW[2][2][4];   // [plane][mf][4]
            #pragma unroll
            for (int p = 0; p < 2; p++)
                #pragma unroll
                for (int mf = 0; mf < 2; mf++)
                    ldsm_x4(aW[p][mf],
                        sb + bufC + p * PQ_PLANE
                           + (wM * 32 + mf * 16 + arow) * 80 + kk * 32 + acol);

            #pragma unroll
            for (int jp = 0; jp < 2; jp++) {
                uint32_t bh4[4];
                const uint32_t baddr = (wN * 32 + jp * 16 + bsel16 + brow) * 80
                                     + kk * 32 + bsel8;
                ldsm_x4(bh4, sb + bufC + 2 * PQ_PLANE + baddr);
                #pragma unroll
                for (int mf = 0; mf < 2; mf++) {
                    mma_f16(racc[mf][2*jp],   aW[0][mf], bh4[0], bh4[1]);
                    mma_f16(racc[mf][2*jp+1], aW[0][mf], bh4[2], bh4[3]);
                    mma_f16(racc[mf][2*jp],   aW[1][mf], bh4[0], bh4[1]);
                    mma_f16(racc[mf][2*jp+1], aW[1][mf], bh4[2], bh4[3]);
                }
            }
        }
        __syncthreads();
    }

    // epilogue: fp16 store with q pre-scale
    #pragma unroll
    for (int mf = 0; mf < 2; mf++) {
        #pragma unroll
        for (int half = 0; half < 2; half++) {
            const int o = m0 + wM * 32 + mf * 16 + g + half * 8;
            const int wi = o >> 8, oc = o & 255;
            const float* bp = (wi == 0) ? bias0 : (wi == 1) ? bias1 : bias2;
            const float bia = bp[oc];
            const float sc = (wi == 0) ? LOG2E : 1.0f;
            #pragma unroll
            for (int j = 0; j < 4; j++) {
                const int n = n0 + wN * 32 + j * 8 + tq * 2;
                const size_t idx = (((size_t)wi * B_ + b) * C_ + oc) * HW_ + n;
                const __half h0 =
                    __float2half_rn((racc[mf][j][half * 2 + 0] + bia) * sc);
                const __half h1 =
                    __float2half_rn((racc[mf][j][half * 2 + 1] + bia) * sc);
                *(__half2*)&g_qkv[idx] = __half2(h0, h1);
            }
        }
    }
}

// ===========================================================================
// Output projection: 3-term bf16, out = gamma*(Wo@a + bo) + x.
// 512 threads, tile 128x128, warp tile 32x32.
// ===========================================================================
#define PJ_PLANE 10240          // 128 rows x 80B
#define PJ_BUF   40960          // 4 planes
#define PJ_SMEM  81920

__global__ __launch_bounds__(512) void outproj_kernel(
    const float* __restrict__ bias,
    float* __restrict__ dstf, const float* __restrict__ resid,
    const float* __restrict__ gamma)
{
    extern __shared__ char smem[];
    const uint32_t sb = smem_u32(smem);

    const int n0 = blockIdx.x << 7;
    const int m0 = blockIdx.y << 7;
    const int b  = blockIdx.z;
    const int t  = threadIdx.x;
    const int w  = t >> 5, lane = t & 31;
    const int wM = w & 3, wN = w >> 2;
    const int g = lane >> 2, tq = lane & 3;

    auto load_buf = [&](int kc, uint32_t bufo) {
        #pragma unroll
        for (int i = 0; i < 4; i++) {
            const int idx = t + (i << 9);
            const int p = idx >> 9;
            const int r = idx & 511;
            const int row = r >> 2, ch = r & 3;
            const __nv_bfloat16* src;
            if (p < 2) src = (p ? g_wo_l : g_wo_h)
                           + (size_t)(m0 + row) * C_ + kc * 32 + ch * 8;
            else       src = (p == 3 ? g_aol : g_aoh)
                           + ((size_t)b * HW_ + n0 + row) * C_ + kc * 32 + ch * 8;
            cp16(sb + bufo + p * PJ_PLANE + row * 80 + ch * 16, src);
        }
        CP_COMMIT();
    };

    load_buf(0, 0);

    float racc[2][4][4] = {};

    const int arow = (lane & 7) + ((lane >> 3) & 1) * 8;
    const int acol = ((lane >> 4) & 1) * 16;
    const int brow = (lane & 7);
    const int bsel8  = ((lane >> 3) & 1) * 16;
    const int bsel16 = ((lane >> 4) & 1) * 8;

    for (int kc = 0; kc < 8; kc++) {
        const uint32_t bufC = (uint32_t)(kc & 1) * PJ_BUF;
        if (kc < 7) load_buf(kc + 1, (uint32_t)((kc + 1) & 1) * PJ_BUF);
        if (kc < 7) { CP_WAIT(1); } else { CP_WAIT(0); }
        __syncthreads();

        #pragma unroll
        for (int kk = 0; kk < 2; kk++) {
            uint32_t aW[2][2][4];
            #pragma unroll
            for (int p = 0; p < 2; p++)
                #pragma unroll
                for (int mf = 0; mf < 2; mf++)
                    ldsm_x4(aW[p][mf],
                        sb + bufC + p * PJ_PLANE
                           + (wM * 32 + mf * 16 + arow) * 80 + kk * 32 + acol);

            #pragma unroll
            for (int jp = 0; jp < 2; jp++) {
                uint32_t bh4[4], bl4[4];
                const uint32_t baddr = (wN * 32 + jp * 16 + bsel16 + brow) * 80
                                     + kk * 32 + bsel8;
                ldsm_x4(bh4, sb + bufC + 2 * PJ_PLANE + baddr);
                ldsm_x4(bl4, sb + bufC + 3 * PJ_PLANE + baddr);
                #pragma unroll
                for (int mf = 0; mf < 2; mf++) {
                    mma_bf16(racc[mf][2*jp],   aW[0][mf], bh4[0], bh4[1]);
                    mma_bf16(racc[mf][2*jp+1], aW[0][mf], bh4[2], bh4[3]);
                    mma_bf16(racc[mf][2*jp],   aW[1][mf], bh4[0], bh4[1]);
                    mma_bf16(racc[mf][2*jp+1], aW[1][mf], bh4[2], bh4[3]);
                    mma_bf16(racc[mf][2*jp],   aW[0][mf], bl4[0], bl4[1]);
                    mma_bf16(racc[mf][2*jp+1], aW[0][mf], bl4[2], bl4[3]);
                }
            }
        }
        __syncthreads();
    }

    const float gm = gamma[0];
    #pragma unroll
    for (int mf = 0; mf < 2; mf++) {
        #pragma unroll
        for (int half = 0; half < 2; half++) {
            const int o = m0 + wM * 32 + mf * 16 + g + half * 8;
            const float bia = bias[o];
            #pragma unroll
            for (int j = 0; j < 4; j++) {
                const int n = n0 + wN * 32 + j * 8 + tq * 2;
                const size_t idx = ((size_t)b * C_ + o) * HW_ + n;
                const float2 rr = *(const float2*)&resid[idx];
                float2 r;
                r.x = gm * (racc[mf][j][half * 2 + 0] + bia) + rr.x;
                r.y = gm * (racc[mf][j][half * 2 + 1] + bia) + rr.y;
                *(float2*)&dstf[idx] = r;
            }
        }
    }
}

// ===========================================================================
// HMMA flash attention v11: pure fp16 S = q*k, Bc=128, 32-m chunk online
// softmax with WARP-UNIFORM LAZY RESCALE, ex2.f16x2, L via ones-column MMA.
// 256-query CTA, 8 warps x 32 q, 2 CTAs/SM. S in log2 domain.
// ===========================================================================
#define AQ_OFF 0
#define AQ_ROW 528
#define AQ_PLANE (32 * AQ_ROW)                       // 16896 (single plane)
#define AK_OFF AQ_PLANE                              // 16896
#define AKV_ROW 272                                  // 128 m * 2B + 16 pad
#define AKV_PLANE (32 * AKV_ROW)                     // 8704
#define AV_OFF (AK_OFF + 2 * AKV_PLANE)              // 34304 (K dbl-buffered)
#define AT_SMEM (AV_OFF + 2 * AKV_PLANE)             // 51712

__global__ __launch_bounds__(256, 2) void attn_mma_kernel(
    const __half* __restrict__ qkv,
    __nv_bfloat16* __restrict__ oh, __nv_bfloat16* __restrict__ ol)
{
    extern __shared__ char smem[];
    const uint32_t sb = smem_u32(smem);

    const int bh = blockIdx.y;
    const int q0 = blockIdx.x << 8;
    const int t  = threadIdx.x;
    const int w  = t >> 5;
    const int lane = t & 31;
    const int g = lane >> 2, tq = lane & 3;
    const int b = bh >> 3, hh = bh & 7;

    const size_t qoff = (((size_t)0 * B_ + b) * C_ + hh * DH_) * HW_;
    const size_t koff = (((size_t)1 * B_ + b) * C_ + hh * DH_) * HW_;
    const size_t voff = (((size_t)2 * B_ + b) * C_ + hh * DH_) * HW_;
    const __half* qp = qkv + qoff;
    const __half* kp = qkv + koff;
    const __half* vp = qkv + voff;

    // ---- issue Q (1024 cp16) + KV iter0 (1024 cp16: kh, vh)
    {
        #pragma unroll
        for (int i = 0; i < 4; i++) {
            const int idx = t + (i << 8);            // 0..1023
            const int d = idx >> 5, ch = idx & 31;
            cp16(sb + AQ_OFF + d * AQ_ROW + ch * 16,
                 qp + (size_t)d * HW_ + q0 + ch * 8);
        }
        #pragma unroll
        for (int i = 0; i < 4; i++) {
            const int idx = t + (i << 8);
            const int p2 = idx >> 9;           // 0 kh, 1 vh
            const int r = idx & 511;
            const int d = r >> 4, ch = r & 15;
            const __half* src = (p2 ? vp : kp) + (size_t)d * HW_ + ch * 8;
            const uint32_t so = p2 ? AV_OFF : AK_OFF;
            cp16(sb + so + d * AKV_ROW + ch * 16, src);
        }
        CP_COMMIT();
    }
    CP_WAIT(0);
    __syncthreads();

    // lane addressing
    const int qrow = (lane & 7) + ((lane >> 4) << 3);
    const int qsel = ((lane >> 3) & 1) << 3;
    const uint32_t qbase = sb + AQ_OFF + qrow * AQ_ROW + (w * 32 + qsel) * 2;
    const int kRowD = (lane & 7) + ((lane >> 4) << 3);
    const int kColB = ((lane >> 3) & 1) * 16;
    const int vRowP = (lane & 7) + (((lane >> 4) & 1) << 3);
    const int vColB = ((lane >> 3) & 1) * 16;

    float oacc[2][4][4] = {};
    float oL[2][4] = {};
    float M0[2] = { -INFINITY, -INFINITY };
    float M1[2] = { -INFINITY, -INFINITY };
    const uint32_t bOnes = (lane < 4) ? 0x3C003C00u : 0u;   // ones in col 0

    for (int i = 0; i < 32; i++) {
        const uint32_t kBuf = (uint32_t)(i & 1) * AKV_PLANE;
        const uint32_t vBuf = (uint32_t)(i & 1) * AKV_PLANE;
        if (i < 31) {
            const int m0n = (i + 1) << 7;
            const uint32_t kBufN = (uint32_t)((i + 1) & 1) * AKV_PLANE;
            const uint32_t vBufN = (uint32_t)((i + 1) & 1) * AKV_PLANE;
            #pragma unroll
            for (int u = 0; u < 4; u++) {
                const int idx = t + (u << 8);
                const int p2 = idx >> 9;
                const int r = idx & 511;
                const int d = r >> 4, ch = r & 15;
                const __half* src = (p2 ? vp : kp) + (size_t)d * HW_ + m0n + ch * 8;
                const uint32_t so = p2 ? (AV_OFF + vBufN) : (AK_OFF + kBufN);
                cp16(sb + so + d * AKV_ROW + ch * 16, src);
            }
            CP_COMMIT();
            CP_WAIT(1);
        } else {
            CP_WAIT(0);
        }
        __syncthreads();

        // ---- four 32-m chunks
        #pragma unroll
        for (int jc = 0; jc < 4; jc++) {
            float sc[2][4][4] = {};   // [mf][nb 0..3][4]
            #pragma unroll
            for (int s = 0; s < 2; s++) {
                uint32_t aQs[2][4];   // [mf][4]
                #pragma unroll
                for (int mf = 0; mf < 2; mf++)
                    ldsm_x4_t(aQs[mf],
                        qbase + s * 16 * AQ_ROW + mf * 32);
                #pragma unroll
                for (int jpi = 0; jpi < 2; jpi++) {
                    const int jp = jc * 2 + jpi;
                    uint32_t kh4[4];
                    const uint32_t ka = kBuf + ((s << 4) + kRowD) * AKV_ROW
                                      + jp * 32 + kColB;
                    ldsm_x4_t(kh4, sb + AK_OFF + ka);
                    #pragma unroll
                    for (int mf = 0; mf < 2; mf++) {
                        mma_f16(sc[mf][2*jpi],   aQs[mf], kh4[0], kh4[2]);
                        mma_f16(sc[mf][2*jpi+1], aQs[mf], kh4[1], kh4[3]);
                    }
                }
            }

            // ---- online softmax over this 32-m chunk (log2 domain)
            uint32_t ah[2][2][4];   // [mf][jpi][4] packed fp16 P
            #pragma unroll
            for (int mf = 0; mf < 2; mf++) {
                float c0 = fmaxf(
                    fmaxf(fmaxf(sc[mf][0][0], sc[mf][0][1]),
                          fmaxf(sc[mf][1][0], sc[mf][1][1])),
                    fmaxf(fmaxf(sc[mf][2][0], sc[mf][2][1]),
                          fmaxf(sc[mf][3][0], sc[mf][3][1])));
                float c1 = fmaxf(
                    fmaxf(fmaxf(sc[mf][0][2], sc[mf][0][3]),
                          fmaxf(sc[mf][1][2], sc[mf][1][3])),
                    fmaxf(fmaxf(sc[mf][2][2], sc[mf][2][3]),
                          fmaxf(sc[mf][3][2], sc[mf][3][3])));
                c0 = fmaxf(c0, __shfl_xor_sync(0xffffffffu, c0, 1));
                c0 = fmaxf(c0, __shfl_xor_sync(0xffffffffu, c0, 2));
                c1 = fmaxf(c1, __shfl_xor_sync(0xffffffffu, c1, 1));
                c1 = fmaxf(c1, __shfl_xor_sync(0xffffffffu, c1, 2));

                const float Mn0 = fmaxf(M0[mf], c0);
                const float Mn1 = fmaxf(M1[mf], c1);
                // warp-uniform lazy rescale: skipped ops were exact x1.0
                if (__any_sync(0xffffffffu,
                               (Mn0 > M0[mf]) || (Mn1 > M1[mf]))) {
                    const float al0 = fexp2(M0[mf] - Mn0);
                    const float al1 = fexp2(M1[mf] - Mn1);
                    #pragma unroll
                    for (int dj = 0; dj < 4; dj++) {
                        oacc[mf][dj][0] *= al0; oacc[mf][dj][1] *= al0;
                        oacc[mf][dj][2] *= al1; oacc[mf][dj][3] *= al1;
                    }
                    oL[mf][0] *= al0; oL[mf][2] *= al1;
                    M0[mf] = Mn0; M1[mf] = Mn1;
                }

                #pragma unroll
                for (int nb = 0; nb < 4; nb++) {
                    const float t0 = sc[mf][nb][0] - M0[mf];
                    const float t1 = sc[mf][nb][1] - M0[mf];
                    const float t2 = sc[mf][nb][2] - M1[mf];
                    const float t3 = sc[mf][nb][3] - M1[mf];
                    ah[mf][nb >> 1][(nb & 1) * 2 + 0] = ex2h2(packh(t0, t1));
                    ah[mf][nb >> 1][(nb & 1) * 2 + 1] = ex2h2(packh(t2, t3));
                }
            }

            // ---- PV + L-column
            #pragma unroll
            for (int jpi = 0; jpi < 2; jpi++) {
                const int jp = jc * 2 + jpi;
                #pragma unroll
                for (int jpd = 0; jpd < 2; jpd++) {
                    uint32_t vh4[4];
                    ldsm_x4(vh4, sb + AV_OFF + vBuf
                                 + (jpd * 16 + vRowP) * AKV_ROW
                                 + jp * 32 + vColB);
                    #pragma unroll
                    for (int mf = 0; mf < 2; mf++) {
                        mma_f16(oacc[mf][2*jpd],   ah[mf][jpi], vh4[0], vh4[1]);
                        mma_f16(oacc[mf][2*jpd+1], ah[mf][jpi], vh4[2], vh4[3]);
                    }
                }
                #pragma unroll
                for (int mf = 0; mf < 2; mf++)
                    mma_f16(oL[mf], ah[mf][jpi], bOnes, bOnes);
            }
        }
        __syncthreads();
    }

    // ---- epilogue: broadcast L from tq==0 lanes, normalize, split, store
    #pragma unroll
    for (int mf = 0; mf < 2; mf++) {
        const float L0 = __shfl_sync(0xffffffffu, oL[mf][0], lane & 28);
        const float L1 = __shfl_sync(0xffffffffu, oL[mf][2], lane & 28);
        const float inv0 = 1.0f / L0;
        const float inv1 = 1.0f / L1;
        #pragma unroll
        for (int h = 0; h < 2; h++) {
            const float inv = h ? inv1 : inv0;
            const int hw = q0 + w * 32 + mf * 16 + g + h * 8;
            #pragma unroll
            for (int dj = 0; dj < 4; dj++) {
                const int d = 8 * dj + tq * 2;
                const float v0 = oacc[mf][dj][h * 2 + 0] * inv;
                const float v1 = oacc[mf][dj][h * 2 + 1] * inv;
                __nv_bfloat16 h0, l0, h1, l1;
                split1(v0, h0, l0); split1(v1, h1, l1);
                const size_t idx = ((size_t)b * HW_ + hw) * C_ + hh * 32 + d;
                *(__nv_bfloat162*)&oh[idx] = __nv_bfloat162(h0, h1);
                *(__nv_bfloat162*)&ol[idx] = __nv_bfloat162(l0, l1);
            }
        }
    }
}

// ===========================================================================
extern "C" void kernel_launch(void* const* d_in, const int* in_sizes, int n_in,
                              void* d_out, int out_size)
{
    const float* x     = (const float*)d_in[0];
    const float* Wq    = (const float*)d_in[1];
    const float* bq    = (const float*)d_in[2];
    const float* Wk    = (const float*)d_in[3];
    const float* bk    = (const float*)d_in[4];
    const float* Wv    = (const float*)d_in[5];
    const float* bv    = (const float*)d_in[6];
    const float* Wo    = (const float*)d_in[7];
    const float* bo    = (const float*)d_in[8];
    const float* gamma = (const float*)d_in[9];
    float* out = (float*)d_out;

    __nv_bfloat16 *aoh, *aol;
    __half *qkv;
    cudaGetSymbolAddress((void**)&qkv, g_qkv);
    cudaGetSymbolAddress((void**)&aoh, g_aoh);
    cudaGetSymbolAddress((void**)&aol, g_aol);

    cudaFuncSetAttribute(qkvproj_kernel,
                         cudaFuncAttributeMaxDynamicSharedMemorySize, PQ_SMEM);
    cudaFuncSetAttribute(outproj_kernel,
                         cudaFuncAttributeMaxDynamicSharedMemorySize, PJ_SMEM);
    cudaFuncSetAttribute(attn_mma_kernel,
                         cudaFuncAttributeMaxDynamicSharedMemorySize, AT_SMEM);

    wsplit_kernel<<<dim3(256, 4), 256>>>(Wq, Wk, Wv, Wo);
    xcvt_kernel<<<dim3(HW_ / 32, C_ / 32, B_), dim3(32, 8)>>>(x);

    // fused QKV projection: M = 768, 2-term fp16
    qkvproj_kernel<<<dim3(HW_ / 128, 6, B_), 512, PQ_SMEM>>>(bq, bk, bv);

    attn_mma_kernel<<<dim3(HW_ / 256, B_ * NH_), 256, AT_SMEM>>>(
        qkv, aoh, aol);

    // output projection: 3-term bf16 + residual
    outproj_kernel<<<dim3(HW_ / 128, 2, B_), 512, PJ_SMEM>>>(
        bo, out, x, gamma);
}